// round 1
// baseline (speedup 1.0000x reference)
#include <cuda_runtime.h>

// Problem constants
#define BATCH 8
#define C 256          // CIN == COUT
#define KB 4           // deformable branches
#define HH 128
#define WW 128
#define HWS 16384      // HH*WW
#define NPX (BATCH*HWS)

// ---------------- device scratch (static, no runtime allocation) ----------------
__device__ float g_proj[(size_t)NPX * C];   // [b][p][c] pixel-major, 134MB
__device__ float g_feat[(size_t)NPX * C];   // [b][p][c] pixel-major, 134MB
__device__ float g_w2f[C * C];              // BN-folded second GEMM weights [o][c]
__device__ float g_bias2[C];                // BN-folded second GEMM bias [o]
__device__ float4 g_cw[(size_t)BATCH * KB * HWS];  // premultiplied corner weights
__device__ int4   g_idx[(size_t)BATCH * KB * HWS]; // clamped corner pixel indices

// ---------------- prep: fold BN into GEMM2 weights ----------------
__global__ void prep_kernel(const float* __restrict__ out_w, const float* __restrict__ out_b,
                            const float* __restrict__ gamma, const float* __restrict__ beta,
                            const float* __restrict__ rmean, const float* __restrict__ rvar) {
    int o = blockIdx.x;
    int c = threadIdx.x;
    __shared__ float red[C];
    float inv = gamma[c] / sqrtf(rvar[c] + 1e-5f);
    float w = out_w[o * C + c];
    g_w2f[o * C + c] = w * inv;
    red[c] = w * (beta[c] - rmean[c] * inv);
    __syncthreads();
    for (int s = 128; s > 0; s >>= 1) {
        if (c < s) red[c] += red[c + s];
        __syncthreads();
    }
    if (c == 0) g_bias2[o] = red[0] + out_b[o];
}

// ---------------- GEMM common config ----------------
#define BM 128
#define BN 128
#define BKC 16
#define LDSP 132   // padded smem row stride

// GEMM1: proj[b][p][o] = sum_c conv_w[o][c] * x[b][c][p] + conv_b[o]
//   A = x (K-major rows: x[b][c][:] contiguous in p)  -> direct tile copy
//   B = conv_w [o][c] -> transpose load
__global__ __launch_bounds__(256, 2) void gemm1_kernel(
    const float* __restrict__ x, const float* __restrict__ conv_w,
    const float* __restrict__ conv_b) {
    __shared__ float As[2][BKC * LDSP];
    __shared__ float Bs[2][BKC * LDSP];
    const int tid = threadIdx.x;
    const int b  = blockIdx.z;
    const int p0 = blockIdx.x * BM;
    const int o0 = blockIdx.y * BN;
    const float* Ab = x + (size_t)b * C * HWS + p0;
    const float* Bb = conv_w + (size_t)o0 * C;

    const int tm = tid >> 4, tn = tid & 15;
    float acc[8][8];
#pragma unroll
    for (int i = 0; i < 8; i++)
#pragma unroll
        for (int j = 0; j < 8; j++) acc[i][j] = 0.f;

    // A load mapping: kk = tid>>5 (0..7, +8 for second), mm = (tid&31)*4
    const int a_k = tid >> 5;
    const int a_m = (tid & 31) * 4;
    // B transpose-load mapping: n = tid>>1, khalf = (tid&1)*8
    const int b_n = tid >> 1;
    const int b_kh = (tid & 1) * 8;

    float4 av0 = *(const float4*)(Ab + (size_t)a_k * HWS + a_m);
    float4 av1 = *(const float4*)(Ab + (size_t)(a_k + 8) * HWS + a_m);
    float4 bv0 = *(const float4*)(Bb + (size_t)b_n * C + b_kh);
    float4 bv1 = *(const float4*)(Bb + (size_t)b_n * C + b_kh + 4);
    *(float4*)&As[0][a_k * LDSP + a_m] = av0;
    *(float4*)&As[0][(a_k + 8) * LDSP + a_m] = av1;
    {
        float* bs = Bs[0];
        bs[(b_kh + 0) * LDSP + b_n] = bv0.x;
        bs[(b_kh + 1) * LDSP + b_n] = bv0.y;
        bs[(b_kh + 2) * LDSP + b_n] = bv0.z;
        bs[(b_kh + 3) * LDSP + b_n] = bv0.w;
        bs[(b_kh + 4) * LDSP + b_n] = bv1.x;
        bs[(b_kh + 5) * LDSP + b_n] = bv1.y;
        bs[(b_kh + 6) * LDSP + b_n] = bv1.z;
        bs[(b_kh + 7) * LDSP + b_n] = bv1.w;
    }
    __syncthreads();

    for (int t = 0; t < C / BKC; t++) {
        const int cur = t & 1;
        if (t < C / BKC - 1) {
            const int kb = (t + 1) * BKC;
            av0 = *(const float4*)(Ab + (size_t)(kb + a_k) * HWS + a_m);
            av1 = *(const float4*)(Ab + (size_t)(kb + a_k + 8) * HWS + a_m);
            bv0 = *(const float4*)(Bb + (size_t)b_n * C + kb + b_kh);
            bv1 = *(const float4*)(Bb + (size_t)b_n * C + kb + b_kh + 4);
        }
#pragma unroll
        for (int kk = 0; kk < BKC; kk++) {
            float a[8], bb[8];
            *(float4*)&a[0] = *(const float4*)&As[cur][kk * LDSP + tm * 8];
            *(float4*)&a[4] = *(const float4*)&As[cur][kk * LDSP + tm * 8 + 4];
            *(float4*)&bb[0] = *(const float4*)&Bs[cur][kk * LDSP + tn * 8];
            *(float4*)&bb[4] = *(const float4*)&Bs[cur][kk * LDSP + tn * 8 + 4];
#pragma unroll
            for (int i = 0; i < 8; i++)
#pragma unroll
                for (int j = 0; j < 8; j++)
                    acc[i][j] = fmaf(a[i], bb[j], acc[i][j]);
        }
        if (t < C / BKC - 1) {
            const int nxt = cur ^ 1;
            *(float4*)&As[nxt][a_k * LDSP + a_m] = av0;
            *(float4*)&As[nxt][(a_k + 8) * LDSP + a_m] = av1;
            float* bs = Bs[nxt];
            bs[(b_kh + 0) * LDSP + b_n] = bv0.x;
            bs[(b_kh + 1) * LDSP + b_n] = bv0.y;
            bs[(b_kh + 2) * LDSP + b_n] = bv0.z;
            bs[(b_kh + 3) * LDSP + b_n] = bv0.w;
            bs[(b_kh + 4) * LDSP + b_n] = bv1.x;
            bs[(b_kh + 5) * LDSP + b_n] = bv1.y;
            bs[(b_kh + 6) * LDSP + b_n] = bv1.z;
            bs[(b_kh + 7) * LDSP + b_n] = bv1.w;
            __syncthreads();
        }
    }

    // epilogue: proj[b][p0+m][o0+n] = acc + conv_b  (pixel-major, n contiguous)
    const float4 bia0 = *(const float4*)(conv_b + o0 + tn * 8);
    const float4 bia1 = *(const float4*)(conv_b + o0 + tn * 8 + 4);
    float* Cb = g_proj + ((size_t)b * HWS + p0) * C + o0;
#pragma unroll
    for (int i = 0; i < 8; i++) {
        const int m = tm * 8 + i;
        float4 v0 = make_float4(acc[i][0] + bia0.x, acc[i][1] + bia0.y,
                                acc[i][2] + bia0.z, acc[i][3] + bia0.w);
        float4 v1 = make_float4(acc[i][4] + bia1.x, acc[i][5] + bia1.y,
                                acc[i][6] + bia1.z, acc[i][7] + bia1.w);
        *(float4*)(Cb + (size_t)m * C + tn * 8) = v0;
        *(float4*)(Cb + (size_t)m * C + tn * 8 + 4) = v1;
    }
}

// ---------------- aux: flows + softmax weights -> corner indices & weights ----------------
#define ACK 32
__global__ void aux_kernel(const float* __restrict__ x,
                           const float* __restrict__ off_w, const float* __restrict__ off_b,
                           const float* __restrict__ wgt_w, const float* __restrict__ wgt_b) {
    // block: 128 threads, 256 pixels (each thread owns 2 pixels)
    __shared__ float wsi[C * 12];      // interleaved [c][12]
    __shared__ float xs[ACK][256];
    const int tid = threadIdx.x;
    const int b = blockIdx.y;
    const int p0 = blockIdx.x * 256;

    for (int e = tid; e < 2 * C * KB; e += 128) {     // off_w: [(k*2+d)][c]
        int kd = e >> 8;                               // 0..7
        int c = e & 255;
        wsi[c * 12 + kd] = off_w[e];
    }
    for (int e = tid; e < C * KB; e += 128) {          // wgt_w: [k][c]
        int k = e >> 8, c = e & 255;
        wsi[c * 12 + 8 + k] = wgt_w[e];
    }

    float acc0[12], acc1[12];
#pragma unroll
    for (int j = 0; j < 12; j++) { acc0[j] = 0.f; acc1[j] = 0.f; }

    const float* xb = x + (size_t)b * C * HWS;
    for (int cc = 0; cc < C; cc += ACK) {
        __syncthreads();
        for (int e4 = tid; e4 < ACK * 64; e4 += 128) {
            int r = e4 >> 6;
            int p4 = (e4 & 63) * 4;
            *(float4*)&xs[r][p4] = *(const float4*)(xb + (size_t)(cc + r) * HWS + p0 + p4);
        }
        __syncthreads();
#pragma unroll 4
        for (int r = 0; r < ACK; r++) {
            float xv0 = xs[r][tid];
            float xv1 = xs[r][tid + 128];
            const float4* wp = (const float4*)(wsi + (cc + r) * 12);
            float4 wa = wp[0], wb = wp[1], wc = wp[2];
            float w[12] = {wa.x, wa.y, wa.z, wa.w, wb.x, wb.y, wb.z, wb.w,
                           wc.x, wc.y, wc.z, wc.w};
#pragma unroll
            for (int j = 0; j < 12; j++) {
                acc0[j] = fmaf(xv0, w[j], acc0[j]);
                acc1[j] = fmaf(xv1, w[j], acc1[j]);
            }
        }
    }

    // finish both pixels
    for (int half = 0; half < 2; half++) {
        float* a = half ? acc1 : acc0;
        int p = p0 + tid + half * 128;
        int py = p >> 7, px = p & 127;
        // softmax over 4 logits
        float l0 = a[8] + wgt_b[0], l1 = a[9] + wgt_b[1];
        float l2 = a[10] + wgt_b[2], l3 = a[11] + wgt_b[3];
        float mx = fmaxf(fmaxf(l0, l1), fmaxf(l2, l3));
        float e0 = __expf(l0 - mx), e1 = __expf(l1 - mx);
        float e2 = __expf(l2 - mx), e3 = __expf(l3 - mx);
        float invs = 1.f / (e0 + e1 + e2 + e3);
        float wk4[4] = {e0 * invs, e1 * invs, e2 * invs, e3 * invs};
#pragma unroll
        for (int k = 0; k < KB; k++) {
            float vx = (float)px + a[2 * k] + off_b[2 * k];
            float vy = (float)py + a[2 * k + 1] + off_b[2 * k + 1];
            float x0f = floorf(vx), y0f = floorf(vy);
            float wx1 = vx - x0f, wy1 = vy - y0f;
            int x0 = (int)x0f, y0 = (int)y0f;
            bool vx0 = (x0 >= 0) && (x0 <= WW - 1);
            bool vx1 = (x0 + 1 >= 0) && (x0 + 1 <= WW - 1);
            bool vy0 = (y0 >= 0) && (y0 <= HH - 1);
            bool vy1 = (y0 + 1 >= 0) && (y0 + 1 <= HH - 1);
            float wk = wk4[k];
            float w00 = (1.f - wx1) * (1.f - wy1) * wk * (float)(vx0 && vy0);
            float w01 = wx1 * (1.f - wy1) * wk * (float)(vx1 && vy0);
            float w10 = (1.f - wx1) * wy1 * wk * (float)(vx0 && vy1);
            float w11 = wx1 * wy1 * wk * (float)(vx1 && vy1);
            int xc0 = min(max(x0, 0), WW - 1);
            int xc1 = min(max(x0 + 1, 0), WW - 1);
            int yc0 = min(max(y0, 0), HH - 1);
            int yc1 = min(max(y0 + 1, 0), HH - 1);
            size_t off = ((size_t)(b * KB + k)) * HWS + p;
            g_idx[off] = make_int4(yc0 * WW + xc0, yc0 * WW + xc1,
                                   yc1 * WW + xc0, yc1 * WW + xc1);
            g_cw[off] = make_float4(w00, w01, w10, w11);
        }
    }
}

// ---------------- sampling: feat[b][p][c] = proj[b][p][c] + sum_k,corner w * proj[b][idx][c] ----------------
__global__ void sample_kernel() {
    const int warp = threadIdx.x >> 5;
    const int lane = threadIdx.x & 31;
    const size_t pp = (size_t)blockIdx.x * 8 + warp;
    const int b = (int)(pp >> 14);       // HWS = 2^14
    const int p = (int)(pp & 16383);

    const float4* projb = (const float4*)g_proj + (size_t)b * HWS * 64;
    const float4* self = projb + (size_t)p * 64;
    float4 aL = self[lane];
    float4 aH = self[32 + lane];

    const size_t kb = (size_t)b * KB * HWS + p;
#pragma unroll
    for (int k = 0; k < KB; k++) {
        int4 id = g_idx[kb + (size_t)k * HWS];
        float4 w = g_cw[kb + (size_t)k * HWS];
        const float4* r0 = projb + (size_t)id.x * 64;
        const float4* r1 = projb + (size_t)id.y * 64;
        const float4* r2 = projb + (size_t)id.z * 64;
        const float4* r3 = projb + (size_t)id.w * 64;
        float4 v;
        v = r0[lane];      aL.x = fmaf(w.x, v.x, aL.x); aL.y = fmaf(w.x, v.y, aL.y); aL.z = fmaf(w.x, v.z, aL.z); aL.w = fmaf(w.x, v.w, aL.w);
        v = r0[32 + lane]; aH.x = fmaf(w.x, v.x, aH.x); aH.y = fmaf(w.x, v.y, aH.y); aH.z = fmaf(w.x, v.z, aH.z); aH.w = fmaf(w.x, v.w, aH.w);
        v = r1[lane];      aL.x = fmaf(w.y, v.x, aL.x); aL.y = fmaf(w.y, v.y, aL.y); aL.z = fmaf(w.y, v.z, aL.z); aL.w = fmaf(w.y, v.w, aL.w);
        v = r1[32 + lane]; aH.x = fmaf(w.y, v.x, aH.x); aH.y = fmaf(w.y, v.y, aH.y); aH.z = fmaf(w.y, v.z, aH.z); aH.w = fmaf(w.y, v.w, aH.w);
        v = r2[lane];      aL.x = fmaf(w.z, v.x, aL.x); aL.y = fmaf(w.z, v.y, aL.y); aL.z = fmaf(w.z, v.z, aL.z); aL.w = fmaf(w.z, v.w, aL.w);
        v = r2[32 + lane]; aH.x = fmaf(w.z, v.x, aH.x); aH.y = fmaf(w.z, v.y, aH.y); aH.z = fmaf(w.z, v.z, aH.z); aH.w = fmaf(w.z, v.w, aH.w);
        v = r3[lane];      aL.x = fmaf(w.w, v.x, aL.x); aL.y = fmaf(w.w, v.y, aL.y); aL.z = fmaf(w.w, v.z, aL.z); aL.w = fmaf(w.w, v.w, aL.w);
        v = r3[32 + lane]; aH.x = fmaf(w.w, v.x, aH.x); aH.y = fmaf(w.w, v.y, aH.y); aH.z = fmaf(w.w, v.z, aH.z); aH.w = fmaf(w.w, v.w, aH.w);
    }
    float4* fo = (float4*)g_feat + ((size_t)b * HWS + p) * 64;
    fo[lane] = aL;
    fo[32 + lane] = aH;
}

// ---------------- GEMM2: out[b][o][p] = sum_c w2f[o][c] * feat[b][p][c] + bias2[o] ----------------
__global__ __launch_bounds__(256, 2) void gemm2_kernel(float* __restrict__ out) {
    __shared__ float sm[2 * 2 * BKC * LDSP];   // As | Bs, reused as Cs for epilogue
    float* As0 = sm;
    float* As1 = sm + BKC * LDSP;
    float* Bs0 = sm + 2 * BKC * LDSP;
    float* Bs1 = sm + 3 * BKC * LDSP;
    const int tid = threadIdx.x;
    const int b  = blockIdx.z;
    const int p0 = blockIdx.x * BM;
    const int o0 = blockIdx.y * BN;
    const float* Ab = g_feat + ((size_t)b * HWS + p0) * C;
    const float* Bb = g_w2f + (size_t)o0 * C;

    const int tm = tid >> 4, tn = tid & 15;
    float acc[8][8];
#pragma unroll
    for (int i = 0; i < 8; i++)
#pragma unroll
        for (int j = 0; j < 8; j++) acc[i][j] = 0.f;

    const int a_m = tid >> 1;            // transpose load for A
    const int a_kh = (tid & 1) * 8;
    const int b_n = tid >> 1;
    const int b_kh = (tid & 1) * 8;

    float4 av0 = *(const float4*)(Ab + (size_t)a_m * C + a_kh);
    float4 av1 = *(const float4*)(Ab + (size_t)a_m * C + a_kh + 4);
    float4 bv0 = *(const float4*)(Bb + (size_t)b_n * C + b_kh);
    float4 bv1 = *(const float4*)(Bb + (size_t)b_n * C + b_kh + 4);
    {
        As0[(a_kh + 0) * LDSP + a_m] = av0.x; As0[(a_kh + 1) * LDSP + a_m] = av0.y;
        As0[(a_kh + 2) * LDSP + a_m] = av0.z; As0[(a_kh + 3) * LDSP + a_m] = av0.w;
        As0[(a_kh + 4) * LDSP + a_m] = av1.x; As0[(a_kh + 5) * LDSP + a_m] = av1.y;
        As0[(a_kh + 6) * LDSP + a_m] = av1.z; As0[(a_kh + 7) * LDSP + a_m] = av1.w;
        Bs0[(b_kh + 0) * LDSP + b_n] = bv0.x; Bs0[(b_kh + 1) * LDSP + b_n] = bv0.y;
        Bs0[(b_kh + 2) * LDSP + b_n] = bv0.z; Bs0[(b_kh + 3) * LDSP + b_n] = bv0.w;
        Bs0[(b_kh + 4) * LDSP + b_n] = bv1.x; Bs0[(b_kh + 5) * LDSP + b_n] = bv1.y;
        Bs0[(b_kh + 6) * LDSP + b_n] = bv1.z; Bs0[(b_kh + 7) * LDSP + b_n] = bv1.w;
    }
    __syncthreads();

    for (int t = 0; t < C / BKC; t++) {
        float* Asc = (t & 1) ? As1 : As0;
        float* Bsc = (t & 1) ? Bs1 : Bs0;
        if (t < C / BKC - 1) {
            const int kbs = (t + 1) * BKC;
            av0 = *(const float4*)(Ab + (size_t)a_m * C + kbs + a_kh);
            av1 = *(const float4*)(Ab + (size_t)a_m * C + kbs + a_kh + 4);
            bv0 = *(const float4*)(Bb + (size_t)b_n * C + kbs + b_kh);
            bv1 = *(const float4*)(Bb + (size_t)b_n * C + kbs + b_kh + 4);
        }
#pragma unroll
        for (int kk = 0; kk < BKC; kk++) {
            float a[8], bb[8];
            *(float4*)&a[0] = *(const float4*)&Asc[kk * LDSP + tm * 8];
            *(float4*)&a[4] = *(const float4*)&Asc[kk * LDSP + tm * 8 + 4];
            *(float4*)&bb[0] = *(const float4*)&Bsc[kk * LDSP + tn * 8];
            *(float4*)&bb[4] = *(const float4*)&Bsc[kk * LDSP + tn * 8 + 4];
#pragma unroll
            for (int i = 0; i < 8; i++)
#pragma unroll
                for (int j = 0; j < 8; j++)
                    acc[i][j] = fmaf(a[i], bb[j], acc[i][j]);
        }
        if (t < C / BKC - 1) {
            float* Asn = (t & 1) ? As0 : As1;
            float* Bsn = (t & 1) ? Bs0 : Bs1;
            Asn[(a_kh + 0) * LDSP + a_m] = av0.x; Asn[(a_kh + 1) * LDSP + a_m] = av0.y;
            Asn[(a_kh + 2) * LDSP + a_m] = av0.z; Asn[(a_kh + 3) * LDSP + a_m] = av0.w;
            Asn[(a_kh + 4) * LDSP + a_m] = av1.x; Asn[(a_kh + 5) * LDSP + a_m] = av1.y;
            Asn[(a_kh + 6) * LDSP + a_m] = av1.z; Asn[(a_kh + 7) * LDSP + a_m] = av1.w;
            Bsn[(b_kh + 0) * LDSP + b_n] = bv0.x; Bsn[(b_kh + 1) * LDSP + b_n] = bv0.y;
            Bsn[(b_kh + 2) * LDSP + b_n] = bv0.z; Bsn[(b_kh + 3) * LDSP + b_n] = bv0.w;
            Bsn[(b_kh + 4) * LDSP + b_n] = bv1.x; Bsn[(b_kh + 5) * LDSP + b_n] = bv1.y;
            Bsn[(b_kh + 6) * LDSP + b_n] = bv1.z; Bsn[(b_kh + 7) * LDSP + b_n] = bv1.w;
            __syncthreads();
        }
    }

    // epilogue: stage through smem for coalesced channel-major writes out[b][o][p]
    __syncthreads();
    float* Cs = sm;   // 64 x 129 staging
    for (int half = 0; half < 2; half++) {
        if ((tm >> 3) == half) {
#pragma unroll
            for (int i = 0; i < 8; i++) {
                const int mr = (tm & 7) * 8 + i;
#pragma unroll
                for (int j = 0; j < 8; j++)
                    Cs[mr * 129 + tn * 8 + j] = acc[i][j];
            }
        }
        __syncthreads();
        float* Ob = out + ((size_t)b * C + o0) * HWS + p0 + half * 64;
#pragma unroll
        for (int r = 0; r < 32; r++) {
            const int e = r * 256 + tid;
            const int n = e >> 6;
            const int m = e & 63;
            Ob[(size_t)n * HWS + m] = Cs[m * 129 + n] + g_bias2[o0 + n];
        }
        __syncthreads();
    }
}

// ---------------- launch ----------------
extern "C" void kernel_launch(void* const* d_in, const int* in_sizes, int n_in,
                              void* d_out, int out_size) {
    (void)in_sizes; (void)n_in; (void)out_size;
    const float* x      = (const float*)d_in[0];
    const float* conv_w = (const float*)d_in[1];
    const float* conv_b = (const float*)d_in[2];
    const float* off_w  = (const float*)d_in[3];
    const float* off_b  = (const float*)d_in[4];
    const float* wgt_w  = (const float*)d_in[5];
    const float* wgt_b  = (const float*)d_in[6];
    const float* gamma  = (const float*)d_in[7];
    const float* beta   = (const float*)d_in[8];
    const float* rmean  = (const float*)d_in[9];
    const float* rvar   = (const float*)d_in[10];
    const float* out_w  = (const float*)d_in[11];
    const float* out_b  = (const float*)d_in[12];
    float* out = (float*)d_out;

    prep_kernel<<<C, C>>>(out_w, out_b, gamma, beta, rmean, rvar);
    gemm1_kernel<<<dim3(HWS / BM, C / BN, BATCH), 256>>>(x, conv_w, conv_b);
    aux_kernel<<<dim3(HWS / 256, BATCH), 128>>>(x, off_w, off_b, wgt_w, wgt_b);
    sample_kernel<<<NPX / 8, 256>>>();
    gemm2_kernel<<<dim3(HWS / BM, C / BN, BATCH), 256>>>(out);
}

// round 3
// speedup vs baseline: 1.5659x; 1.5659x over previous
#include <cuda_runtime.h>
#include <cuda_bf16.h>
#include <cstdint>

// Problem constants
#define BATCH 8
#define C 256
#define KB 4
#define HH 128
#define WW 128
#define HWS 16384
#define NPX (BATCH*HWS)

// ---------------- device scratch ----------------
__device__ float g_proj[(size_t)NPX * C];                        // [b][p][c] fp32
__device__ __align__(16) __nv_bfloat16 g_feath[(size_t)NPX * C]; // feat hi  [b][p][c]
__device__ __align__(16) __nv_bfloat16 g_featl[(size_t)NPX * C]; // feat lo
__device__ __align__(16) __nv_bfloat16 g_w1h[C * C];             // conv_w hi [o][c]
__device__ __align__(16) __nv_bfloat16 g_w1l[C * C];
__device__ __align__(16) __nv_bfloat16 g_w2h[C * C];             // BN-folded out_w hi [o][c]
__device__ __align__(16) __nv_bfloat16 g_w2l[C * C];
__device__ float g_bias2[C];
__device__ float4 g_cw[(size_t)BATCH * KB * HWS];
__device__ int4   g_idx[(size_t)BATCH * KB * HWS];

// ---------------- helpers ----------------
__device__ __forceinline__ uint32_t smem_u32(const void* p) {
    uint32_t a;
    asm("{ .reg .u64 t; cvta.to.shared.u64 t, %1; cvt.u32.u64 %0, t; }" : "=r"(a) : "l"(p));
    return a;
}

__device__ __forceinline__ void ldsm4(uint32_t* r, uint32_t addr) {
    asm volatile("ldmatrix.sync.aligned.m8n8.x4.shared.b16 {%0,%1,%2,%3}, [%4];"
                 : "=r"(r[0]), "=r"(r[1]), "=r"(r[2]), "=r"(r[3]) : "r"(addr));
}

__device__ __forceinline__ void mma_bf16(float* d, const uint32_t* a, uint32_t b0, uint32_t b1) {
    asm volatile(
        "mma.sync.aligned.m16n8k16.row.col.f32.bf16.bf16.f32 "
        "{%0,%1,%2,%3}, {%4,%5,%6,%7}, {%8,%9}, {%0,%1,%2,%3};"
        : "+f"(d[0]), "+f"(d[1]), "+f"(d[2]), "+f"(d[3])
        : "r"(a[0]), "r"(a[1]), "r"(a[2]), "r"(a[3]), "r"(b0), "r"(b1));
}

__device__ __forceinline__ void split_pack(float a, float b, uint32_t& hi, uint32_t& lo) {
    __nv_bfloat162 h = __floats2bfloat162_rn(a, b);
    float ra = a - __bfloat162float(h.x);
    float rb = b - __bfloat162float(h.y);
    __nv_bfloat162 l = __floats2bfloat162_rn(ra, rb);
    hi = *reinterpret_cast<uint32_t*>(&h);
    lo = *reinterpret_cast<uint32_t*>(&l);
}

// SMEM tile geometry: 128 rows x 32 bf16, row stride 80B (64B data + 16B pad)
#define ROWB 80
#define TSZ  (128 * ROWB)          // 10240 per tile
#define BUFSZ (4 * TSZ)            // AH, AL, BH, BL per buffer = 40960
#define OFF_AH 0
#define OFF_AL TSZ
#define OFF_BH (2 * TSZ)
#define OFF_BL (3 * TSZ)
#define OFF_BIAS (2 * BUFSZ)       // 81920
#define GEMM_SMEM (OFF_BIAS + 1024)

// ---------------- prep: split weights to bf16 hi/lo, fold BN ----------------
__global__ void prep_kernel(const float* __restrict__ conv_w,
                            const float* __restrict__ out_w, const float* __restrict__ out_b,
                            const float* __restrict__ gamma, const float* __restrict__ beta,
                            const float* __restrict__ rmean, const float* __restrict__ rvar) {
    int o = blockIdx.x;
    int c = threadIdx.x;
    __shared__ float red[C];
    float w1 = conv_w[o * C + c];
    __nv_bfloat16 h1 = __float2bfloat16(w1);
    g_w1h[o * C + c] = h1;
    g_w1l[o * C + c] = __float2bfloat16(w1 - __bfloat162float(h1));

    float inv = gamma[c] / sqrtf(rvar[c] + 1e-5f);
    float w = out_w[o * C + c];
    float w2 = w * inv;
    __nv_bfloat16 h2 = __float2bfloat16(w2);
    g_w2h[o * C + c] = h2;
    g_w2l[o * C + c] = __float2bfloat16(w2 - __bfloat162float(h2));

    red[c] = w * (beta[c] - rmean[c] * inv);
    __syncthreads();
    for (int s = 128; s > 0; s >>= 1) {
        if (c < s) red[c] += red[c + s];
        __syncthreads();
    }
    if (c == 0) g_bias2[o] = red[0] + out_b[o];
}

// ---------------- shared mma tile step ----------------
// computes one BK=32 chunk (two k16 sub-steps) into acc[2][8][4]
__device__ __forceinline__ void mma_chunk(float acc[2][8][4], uint32_t smbuf,
                                          int warp_m, int warp_n, int lr, int lc) {
    const uint32_t a_base = smbuf + OFF_AH + (uint32_t)(warp_m * 32 + lr) * ROWB + lc * 16;
    const uint32_t b_base = smbuf + OFF_BH + (uint32_t)(warp_n * 64 + lr) * ROWB + lc * 16;
#pragma unroll
    for (int s = 0; s < 2; s++) {
        uint32_t ah[2][4], al[2][4];
        uint32_t bh[4][4], bl[4][4];
#pragma unroll
        for (int t = 0; t < 2; t++) {
            ldsm4(ah[t], a_base + t * (16 * ROWB) + s * 32);
            ldsm4(al[t], a_base + TSZ + t * (16 * ROWB) + s * 32);
        }
#pragma unroll
        for (int u = 0; u < 4; u++) {
            ldsm4(bh[u], b_base + u * (16 * ROWB) + s * 32);
            ldsm4(bl[u], b_base + TSZ + u * (16 * ROWB) + s * 32);
        }
        // pass 0: Ah*Bh
#pragma unroll
        for (int t = 0; t < 2; t++)
#pragma unroll
            for (int u = 0; u < 4; u++) {
                mma_bf16(acc[t][u * 2], ah[t], bh[u][0], bh[u][2]);
                mma_bf16(acc[t][u * 2 + 1], ah[t], bh[u][1], bh[u][3]);
            }
        // pass 1: Ah*Bl
#pragma unroll
        for (int t = 0; t < 2; t++)
#pragma unroll
            for (int u = 0; u < 4; u++) {
                mma_bf16(acc[t][u * 2], ah[t], bl[u][0], bl[u][2]);
                mma_bf16(acc[t][u * 2 + 1], ah[t], bl[u][1], bl[u][3]);
            }
        // pass 2: Al*Bh
#pragma unroll
        for (int t = 0; t < 2; t++)
#pragma unroll
            for (int u = 0; u < 4; u++) {
                mma_bf16(acc[t][u * 2], al[t], bh[u][0], bh[u][2]);
                mma_bf16(acc[t][u * 2 + 1], al[t], bh[u][1], bh[u][3]);
            }
    }
}

// ---------------- GEMM1: proj[b][p][o] = x^T @ conv_w^T + conv_b ----------------
struct PF1 {
    uint32_t ah[8], al[8];
    int4 bh[2], bl[2];
};

__device__ __forceinline__ void pf1_load(PF1& f, const float* __restrict__ xb,
                                         const __nv_bfloat16* __restrict__ wh,
                                         const __nv_bfloat16* __restrict__ wl,
                                         int kc, int am, int ach, int tid) {
#pragma unroll
    for (int i = 0; i < 8; i++) {
        int cl = ach * 16 + i * 2;
        float v0 = xb[(size_t)(kc + cl) * HWS + am];
        float v1 = xb[(size_t)(kc + cl + 1) * HWS + am];
        split_pack(v0, v1, f.ah[i], f.al[i]);
    }
#pragma unroll
    for (int j = 0; j < 2; j++) {
        int e = j * 256 + tid;
        int row = e >> 2, ch = e & 3;
        f.bh[j] = *(const int4*)(wh + (size_t)row * C + kc + ch * 8);
        f.bl[j] = *(const int4*)(wl + (size_t)row * C + kc + ch * 8);
    }
}

__device__ __forceinline__ void pf1_store(const PF1& f, char* base, int am, int ach, int tid) {
#pragma unroll
    for (int i = 0; i < 8; i++) {
        int cl = ach * 16 + i * 2;
        *(uint32_t*)(base + OFF_AH + am * ROWB + cl * 2) = f.ah[i];
        *(uint32_t*)(base + OFF_AL + am * ROWB + cl * 2) = f.al[i];
    }
#pragma unroll
    for (int j = 0; j < 2; j++) {
        int e = j * 256 + tid;
        int row = e >> 2, ch = e & 3;
        *(int4*)(base + OFF_BH + row * ROWB + ch * 16) = f.bh[j];
        *(int4*)(base + OFF_BL + row * ROWB + ch * 16) = f.bl[j];
    }
}

__global__ __launch_bounds__(256) void gemm1_mma(const float* __restrict__ x,
                                                 const float* __restrict__ conv_b) {
    extern __shared__ char sm[];
    const uint32_t smb = smem_u32(sm);
    const int tid = threadIdx.x;
    const int wid = tid >> 5, lane = tid & 31;
    const int warp_m = wid & 3, warp_n = wid >> 2;
    const int lr = lane & 15, lc = lane >> 4;
    const int p0 = blockIdx.x * 128, o0 = blockIdx.y * 128, b = blockIdx.z;

    if (tid < 128) ((float*)(sm + OFF_BIAS))[tid] = conv_b[o0 + tid];

    const float* xb = x + (size_t)b * C * HWS + p0;
    const __nv_bfloat16* wh = g_w1h + (size_t)o0 * C;
    const __nv_bfloat16* wl = g_w1l + (size_t)o0 * C;
    const int am = tid & 127, ach = tid >> 7;

    float acc[2][8][4];
#pragma unroll
    for (int t = 0; t < 2; t++)
#pragma unroll
        for (int j = 0; j < 8; j++)
#pragma unroll
            for (int q = 0; q < 4; q++) acc[t][j][q] = 0.f;

    PF1 f;
    pf1_load(f, xb, wh, wl, 0, am, ach, tid);
    pf1_store(f, sm, am, ach, tid);
    __syncthreads();

    for (int kt = 0; kt < 8; kt++) {
        const int buf = kt & 1;
        if (kt < 7) pf1_load(f, xb, wh, wl, (kt + 1) * 32, am, ach, tid);
        mma_chunk(acc, smb + buf * BUFSZ, warp_m, warp_n, lr, lc);
        if (kt < 7) {
            pf1_store(f, sm + (buf ^ 1) * BUFSZ, am, ach, tid);
            __syncthreads();
        }
    }

    // epilogue: write proj [b][p][o] + bias
    const float* sbias = (const float*)(sm + OFF_BIAS);
    float* Cb = g_proj + ((size_t)b * HWS + p0) * C + o0;
    const int g4 = lane >> 2, tg = lane & 3;
#pragma unroll
    for (int t = 0; t < 2; t++) {
        const int r0 = warp_m * 32 + t * 16 + g4;
#pragma unroll
        for (int j = 0; j < 8; j++) {
            const int oc = warp_n * 64 + j * 8 + tg * 2;
            float b0 = sbias[oc], b1 = sbias[oc + 1];
            float2 v0 = make_float2(acc[t][j][0] + b0, acc[t][j][1] + b1);
            float2 v1 = make_float2(acc[t][j][2] + b0, acc[t][j][3] + b1);
            *(float2*)(Cb + (size_t)r0 * C + oc) = v0;
            *(float2*)(Cb + (size_t)(r0 + 8) * C + oc) = v1;
        }
    }
}

// ---------------- GEMM2: out[b][o][p] = feat @ w2f^T + bias2 ----------------
struct PF2 {
    int4 ah[2], al[2], bh[2], bl[2];
};

__device__ __forceinline__ void pf2_load(PF2& f, const __nv_bfloat16* __restrict__ fh,
                                         const __nv_bfloat16* __restrict__ fl,
                                         const __nv_bfloat16* __restrict__ wh,
                                         const __nv_bfloat16* __restrict__ wl,
                                         int kc, int tid) {
#pragma unroll
    for (int j = 0; j < 2; j++) {
        int e = j * 256 + tid;
        int row = e >> 2, ch = e & 3;
        f.ah[j] = *(const int4*)(fh + (size_t)row * C + kc + ch * 8);
        f.al[j] = *(const int4*)(fl + (size_t)row * C + kc + ch * 8);
        f.bh[j] = *(const int4*)(wh + (size_t)row * C + kc + ch * 8);
        f.bl[j] = *(const int4*)(wl + (size_t)row * C + kc + ch * 8);
    }
}

__device__ __forceinline__ void pf2_store(const PF2& f, char* base, int tid) {
#pragma unroll
    for (int j = 0; j < 2; j++) {
        int e = j * 256 + tid;
        int row = e >> 2, ch = e & 3;
        *(int4*)(base + OFF_AH + row * ROWB + ch * 16) = f.ah[j];
        *(int4*)(base + OFF_AL + row * ROWB + ch * 16) = f.al[j];
        *(int4*)(base + OFF_BH + row * ROWB + ch * 16) = f.bh[j];
        *(int4*)(base + OFF_BL + row * ROWB + ch * 16) = f.bl[j];
    }
}

__global__ __launch_bounds__(256) void gemm2_mma(float* __restrict__ out) {
    extern __shared__ char sm[];
    const uint32_t smb = smem_u32(sm);
    const int tid = threadIdx.x;
    const int wid = tid >> 5, lane = tid & 31;
    const int warp_m = wid & 3, warp_n = wid >> 2;
    const int lr = lane & 15, lc = lane >> 4;
    const int p0 = blockIdx.x * 128, o0 = blockIdx.y * 128, b = blockIdx.z;

    if (tid < 128) ((float*)(sm + OFF_BIAS))[tid] = g_bias2[o0 + tid];

    const __nv_bfloat16* fh = g_feath + ((size_t)b * HWS + p0) * C;
    const __nv_bfloat16* fl = g_featl + ((size_t)b * HWS + p0) * C;
    const __nv_bfloat16* wh = g_w2h + (size_t)o0 * C;
    const __nv_bfloat16* wl = g_w2l + (size_t)o0 * C;

    float acc[2][8][4];
#pragma unroll
    for (int t = 0; t < 2; t++)
#pragma unroll
        for (int j = 0; j < 8; j++)
#pragma unroll
            for (int q = 0; q < 4; q++) acc[t][j][q] = 0.f;

    PF2 f;
    pf2_load(f, fh, fl, wh, wl, 0, tid);
    pf2_store(f, sm, tid);
    __syncthreads();

    for (int kt = 0; kt < 8; kt++) {
        const int buf = kt & 1;
        if (kt < 7) pf2_load(f, fh, fl, wh, wl, (kt + 1) * 32, tid);
        mma_chunk(acc, smb + buf * BUFSZ, warp_m, warp_n, lr, lc);
        if (kt < 7) {
            pf2_store(f, sm + (buf ^ 1) * BUFSZ, tid);
            __syncthreads();
        }
    }

    // epilogue: transpose through smem -> channel-major out[b][o][p]
    __syncthreads();
    float* Cs = (float*)sm;   // 128 x 33 staging
    const float* sbias = (const float*)(sm + OFF_BIAS);
    float* Ob = out + ((size_t)b * C + o0) * HWS + p0;
    const int g4 = lane >> 2, tg = lane & 3;
#pragma unroll
    for (int g = 0; g < 4; g++) {
        if (warp_n == (g >> 1)) {
#pragma unroll
            for (int t = 0; t < 2; t++)
#pragma unroll
                for (int jj = 0; jj < 4; jj++) {
                    const int j = (g & 1) * 4 + jj;
                    const int r = warp_m * 32 + t * 16 + g4;
                    const int cl = jj * 8 + tg * 2;
                    Cs[r * 33 + cl] = acc[t][j][0];
                    Cs[r * 33 + cl + 1] = acc[t][j][1];
                    Cs[(r + 8) * 33 + cl] = acc[t][j][2];
                    Cs[(r + 8) * 33 + cl + 1] = acc[t][j][3];
                }
        }
        __syncthreads();
#pragma unroll
        for (int q = 0; q < 16; q++) {
            const int e = q * 256 + tid;
            const int col = e >> 7, mm = e & 127;
            const int oc = g * 32 + col;
            Ob[(size_t)oc * HWS + mm] = Cs[mm * 33 + col] + sbias[oc];
        }
        __syncthreads();
    }
}

// ---------------- aux: flows + softmax weights -> corner indices & weights ----------------
#define ACK 32
__global__ void aux_kernel(const float* __restrict__ x,
                           const float* __restrict__ off_w, const float* __restrict__ off_b,
                           const float* __restrict__ wgt_w, const float* __restrict__ wgt_b) {
    __shared__ float wsi[C * 12];
    __shared__ float xs[ACK][256];
    const int tid = threadIdx.x;
    const int b = blockIdx.y;
    const int p0 = blockIdx.x * 256;

    for (int e = tid; e < 2 * C * KB; e += 128) {
        int kd = e >> 8;
        int c = e & 255;
        wsi[c * 12 + kd] = off_w[e];
    }
    for (int e = tid; e < C * KB; e += 128) {
        int k = e >> 8, c = e & 255;
        wsi[c * 12 + 8 + k] = wgt_w[e];
    }

    float acc0[12], acc1[12];
#pragma unroll
    for (int j = 0; j < 12; j++) { acc0[j] = 0.f; acc1[j] = 0.f; }

    const float* xb = x + (size_t)b * C * HWS;
    for (int cc = 0; cc < C; cc += ACK) {
        __syncthreads();
        for (int e4 = tid; e4 < ACK * 64; e4 += 128) {
            int r = e4 >> 6;
            int p4 = (e4 & 63) * 4;
            *(float4*)&xs[r][p4] = *(const float4*)(xb + (size_t)(cc + r) * HWS + p0 + p4);
        }
        __syncthreads();
#pragma unroll 4
        for (int r = 0; r < ACK; r++) {
            float xv0 = xs[r][tid];
            float xv1 = xs[r][tid + 128];
            const float4* wp = (const float4*)(wsi + (cc + r) * 12);
            float4 wa = wp[0], wb = wp[1], wc = wp[2];
            float w[12] = {wa.x, wa.y, wa.z, wa.w, wb.x, wb.y, wb.z, wb.w,
                           wc.x, wc.y, wc.z, wc.w};
#pragma unroll
            for (int j = 0; j < 12; j++) {
                acc0[j] = fmaf(xv0, w[j], acc0[j]);
                acc1[j] = fmaf(xv1, w[j], acc1[j]);
            }
        }
    }

    for (int half = 0; half < 2; half++) {
        float* a = half ? acc1 : acc0;
        int p = p0 + tid + half * 128;
        int py = p >> 7, px = p & 127;
        float l0 = a[8] + wgt_b[0], l1 = a[9] + wgt_b[1];
        float l2 = a[10] + wgt_b[2], l3 = a[11] + wgt_b[3];
        float mx = fmaxf(fmaxf(l0, l1), fmaxf(l2, l3));
        float e0 = __expf(l0 - mx), e1 = __expf(l1 - mx);
        float e2 = __expf(l2 - mx), e3 = __expf(l3 - mx);
        float invs = 1.f / (e0 + e1 + e2 + e3);
        float wk4[4] = {e0 * invs, e1 * invs, e2 * invs, e3 * invs};
#pragma unroll
        for (int k = 0; k < KB; k++) {
            float vx = (float)px + a[2 * k] + off_b[2 * k];
            float vy = (float)py + a[2 * k + 1] + off_b[2 * k + 1];
            float x0f = floorf(vx), y0f = floorf(vy);
            float wx1 = vx - x0f, wy1 = vy - y0f;
            int x0 = (int)x0f, y0 = (int)y0f;
            bool vx0 = (x0 >= 0) && (x0 <= WW - 1);
            bool vx1 = (x0 + 1 >= 0) && (x0 + 1 <= WW - 1);
            bool vy0 = (y0 >= 0) && (y0 <= HH - 1);
            bool vy1 = (y0 + 1 >= 0) && (y0 + 1 <= HH - 1);
            float wk = wk4[k];
            float w00 = (1.f - wx1) * (1.f - wy1) * wk * (float)(vx0 && vy0);
            float w01 = wx1 * (1.f - wy1) * wk * (float)(vx1 && vy0);
            float w10 = (1.f - wx1) * wy1 * wk * (float)(vx0 && vy1);
            float w11 = wx1 * wy1 * wk * (float)(vx1 && vy1);
            int xc0 = min(max(x0, 0), WW - 1);
            int xc1 = min(max(x0 + 1, 0), WW - 1);
            int yc0 = min(max(y0, 0), HH - 1);
            int yc1 = min(max(y0 + 1, 0), HH - 1);
            size_t off = ((size_t)(b * KB + k)) * HWS + p;
            g_idx[off] = make_int4(yc0 * WW + xc0, yc0 * WW + xc1,
                                   yc1 * WW + xc0, yc1 * WW + xc1);
            g_cw[off] = make_float4(w00, w01, w10, w11);
        }
    }
}

// ---------------- sampling: feat = proj + weighted gather; emit bf16 hi/lo ----------------
__global__ void sample_kernel() {
    const int warp = threadIdx.x >> 5;
    const int lane = threadIdx.x & 31;
    const size_t pp = (size_t)blockIdx.x * 8 + warp;
    const int b = (int)(pp >> 14);
    const int p = (int)(pp & 16383);

    const float4* projb = (const float4*)g_proj + (size_t)b * HWS * 64;
    const float4* self = projb + (size_t)p * 64;
    float4 aL = self[lane];
    float4 aH = self[32 + lane];

    const size_t kb = (size_t)b * KB * HWS + p;
#pragma unroll
    for (int k = 0; k < KB; k++) {
        int4 id = g_idx[kb + (size_t)k * HWS];
        float4 w = g_cw[kb + (size_t)k * HWS];
        const float4* r0 = projb + (size_t)id.x * 64;
        const float4* r1 = projb + (size_t)id.y * 64;
        const float4* r2 = projb + (size_t)id.z * 64;
        const float4* r3 = projb + (size_t)id.w * 64;
        float4 v;
        v = r0[lane];      aL.x = fmaf(w.x, v.x, aL.x); aL.y = fmaf(w.x, v.y, aL.y); aL.z = fmaf(w.x, v.z, aL.z); aL.w = fmaf(w.x, v.w, aL.w);
        v = r0[32 + lane]; aH.x = fmaf(w.x, v.x, aH.x); aH.y = fmaf(w.x, v.y, aH.y); aH.z = fmaf(w.x, v.z, aH.z); aH.w = fmaf(w.x, v.w, aH.w);
        v = r1[lane];      aL.x = fmaf(w.y, v.x, aL.x); aL.y = fmaf(w.y, v.y, aL.y); aL.z = fmaf(w.y, v.z, aL.z); aL.w = fmaf(w.y, v.w, aL.w);
        v = r1[32 + lane]; aH.x = fmaf(w.y, v.x, aH.x); aH.y = fmaf(w.y, v.y, aH.y); aH.z = fmaf(w.y, v.z, aH.z); aH.w = fmaf(w.y, v.w, aH.w);
        v = r2[lane];      aL.x = fmaf(w.z, v.x, aL.x); aL.y = fmaf(w.z, v.y, aL.y); aL.z = fmaf(w.z, v.z, aL.z); aL.w = fmaf(w.z, v.w, aL.w);
        v = r2[32 + lane]; aH.x = fmaf(w.z, v.x, aH.x); aH.y = fmaf(w.z, v.y, aH.y); aH.z = fmaf(w.z, v.z, aH.z); aH.w = fmaf(w.z, v.w, aH.w);
        v = r3[lane];      aL.x = fmaf(w.w, v.x, aL.x); aL.y = fmaf(w.w, v.y, aL.y); aL.z = fmaf(w.w, v.z, aL.z); aL.w = fmaf(w.w, v.w, aL.w);
        v = r3[32 + lane]; aH.x = fmaf(w.w, v.x, aH.x); aH.y = fmaf(w.w, v.y, aH.y); aH.z = fmaf(w.w, v.z, aH.z); aH.w = fmaf(w.w, v.w, aH.w);
    }
    const size_t base = ((size_t)b * HWS + p) * C;
    uint32_t h0, l0, h1, l1;
    split_pack(aL.x, aL.y, h0, l0);
    split_pack(aL.z, aL.w, h1, l1);
    *(uint2*)&g_feath[base + lane * 4] = make_uint2(h0, h1);
    *(uint2*)&g_featl[base + lane * 4] = make_uint2(l0, l1);
    split_pack(aH.x, aH.y, h0, l0);
    split_pack(aH.z, aH.w, h1, l1);
    *(uint2*)&g_feath[base + 128 + lane * 4] = make_uint2(h0, h1);
    *(uint2*)&g_featl[base + 128 + lane * 4] = make_uint2(l0, l1);
}

// ---------------- launch ----------------
extern "C" void kernel_launch(void* const* d_in, const int* in_sizes, int n_in,
                              void* d_out, int out_size) {
    (void)in_sizes; (void)n_in; (void)out_size;
    const float* x      = (const float*)d_in[0];
    const float* conv_w = (const float*)d_in[1];
    const float* conv_b = (const float*)d_in[2];
    const float* off_w  = (const float*)d_in[3];
    const float* off_b  = (const float*)d_in[4];
    const float* wgt_w  = (const float*)d_in[5];
    const float* wgt_b  = (const float*)d_in[6];
    const float* gamma  = (const float*)d_in[7];
    const float* beta   = (const float*)d_in[8];
    const float* rmean  = (const float*)d_in[9];
    const float* rvar   = (const float*)d_in[10];
    const float* out_w  = (const float*)d_in[11];
    const float* out_b  = (const float*)d_in[12];
    float* out = (float*)d_out;

    static bool attr_done = false;
    if (!attr_done) {
        cudaFuncSetAttribute(gemm1_mma, cudaFuncAttributeMaxDynamicSharedMemorySize, GEMM_SMEM);
        cudaFuncSetAttribute(gemm2_mma, cudaFuncAttributeMaxDynamicSharedMemorySize, GEMM_SMEM);
        attr_done = true;
    }

    prep_kernel<<<C, C>>>(conv_w, out_w, out_b, gamma, beta, rmean, rvar);
    gemm1_mma<<<dim3(HWS / 128, C / 128, BATCH), 256, GEMM_SMEM>>>(x, conv_b);
    aux_kernel<<<dim3(HWS / 256, BATCH), 128>>>(x, off_w, off_b, wgt_w, wgt_b);
    sample_kernel<<<NPX / 8, 256>>>();
    gemm2_mma<<<dim3(HWS / 128, C / 128, BATCH), 256, GEMM_SMEM>>>(out);
}

// round 4
// speedup vs baseline: 2.1964x; 1.4026x over previous
#include <cuda_runtime.h>
#include <cuda_fp16.h>
#include <cstdint>

// Problem constants
#define BATCH 8
#define C 256
#define KB 4
#define HH 128
#define WW 128
#define HWS 16384
#define NPX (BATCH*HWS)

// ---------------- device scratch ----------------
__device__ float g_proj[(size_t)NPX * C];                  // [b][p][c] fp32
__device__ __align__(16) __half g_feat[(size_t)NPX * C];   // feat fp16 [b][p][c]
__device__ __align__(16) __half g_w1h[C * C];              // conv_w hi fp16 [o][c]
__device__ __align__(16) __half g_w1l[C * C];              // conv_w lo fp16
__device__ __align__(16) __half g_w2h[C * C];              // BN-folded out_w hi [o][c]
__device__ __align__(16) __half g_w2l[C * C];
__device__ float g_bias2[C];
__device__ float4 g_cw[(size_t)BATCH * KB * HWS];
__device__ int4   g_idx[(size_t)BATCH * KB * HWS];

// ---------------- helpers ----------------
__device__ __forceinline__ uint32_t smem_u32(const void* p) {
    uint32_t a;
    asm("{ .reg .u64 t; cvta.to.shared.u64 t, %1; cvt.u32.u64 %0, t; }" : "=r"(a) : "l"(p));
    return a;
}

__device__ __forceinline__ void ldsm4(uint32_t* r, uint32_t addr) {
    asm volatile("ldmatrix.sync.aligned.m8n8.x4.shared.b16 {%0,%1,%2,%3}, [%4];"
                 : "=r"(r[0]), "=r"(r[1]), "=r"(r[2]), "=r"(r[3]) : "r"(addr));
}

__device__ __forceinline__ void mma_fp16(float* d, const uint32_t* a, uint32_t b0, uint32_t b1) {
    asm volatile(
        "mma.sync.aligned.m16n8k16.row.col.f32.f16.f16.f32 "
        "{%0,%1,%2,%3}, {%4,%5,%6,%7}, {%8,%9}, {%0,%1,%2,%3};"
        : "+f"(d[0]), "+f"(d[1]), "+f"(d[2]), "+f"(d[3])
        : "r"(a[0]), "r"(a[1]), "r"(a[2]), "r"(a[3]), "r"(b0), "r"(b1));
}

// SMEM tile geometry: 128 rows x 32 fp16, row stride 80B (64B data + 16B pad)
#define ROWB 80
#define TSZ  (128 * ROWB)          // 10240 per tile
#define BUFSZ (3 * TSZ)            // A, BH, BL per buffer = 30720
#define OFF_A  0
#define OFF_BH TSZ
#define OFF_BL (2 * TSZ)
#define OFF_BIAS (2 * BUFSZ)       // 61440
#define GEMM_SMEM (OFF_BIAS + 1024)

// ---------------- prep: split weights to fp16 hi/lo, fold BN ----------------
__global__ void prep_kernel(const float* __restrict__ conv_w,
                            const float* __restrict__ out_w, const float* __restrict__ out_b,
                            const float* __restrict__ gamma, const float* __restrict__ beta,
                            const float* __restrict__ rmean, const float* __restrict__ rvar) {
    int o = blockIdx.x;
    int c = threadIdx.x;
    __shared__ float red[C];
    float w1 = conv_w[o * C + c];
    __half h1 = __float2half_rn(w1);
    g_w1h[o * C + c] = h1;
    g_w1l[o * C + c] = __float2half_rn(w1 - __half2float(h1));

    float inv = gamma[c] / sqrtf(rvar[c] + 1e-5f);
    float w = out_w[o * C + c];
    float w2 = w * inv;
    __half h2 = __float2half_rn(w2);
    g_w2h[o * C + c] = h2;
    g_w2l[o * C + c] = __float2half_rn(w2 - __half2float(h2));

    red[c] = w * (beta[c] - rmean[c] * inv);
    __syncthreads();
    for (int s = 128; s > 0; s >>= 1) {
        if (c < s) red[c] += red[c + s];
        __syncthreads();
    }
    if (c == 0) g_bias2[o] = red[0] + out_b[o];
}

// ---------------- shared mma tile step (2-pass: A * (Bh + Bl)) ----------------
__device__ __forceinline__ void mma_chunk(float acc[2][8][4], uint32_t smbuf,
                                          int warp_m, int warp_n, int lr, int lc) {
    const uint32_t a_base = smbuf + OFF_A + (uint32_t)(warp_m * 32 + lr) * ROWB + lc * 16;
    const uint32_t b_base = smbuf + OFF_BH + (uint32_t)(warp_n * 64 + lr) * ROWB + lc * 16;
#pragma unroll
    for (int s = 0; s < 2; s++) {
        uint32_t a[2][4];
        uint32_t bh[4][4], bl[4][4];
#pragma unroll
        for (int t = 0; t < 2; t++)
            ldsm4(a[t], a_base + t * (16 * ROWB) + s * 32);
#pragma unroll
        for (int u = 0; u < 4; u++) {
            ldsm4(bh[u], b_base + u * (16 * ROWB) + s * 32);
            ldsm4(bl[u], b_base + TSZ + u * (16 * ROWB) + s * 32);
        }
        // pass 0: A*Bh
#pragma unroll
        for (int t = 0; t < 2; t++)
#pragma unroll
            for (int u = 0; u < 4; u++) {
                mma_fp16(acc[t][u * 2], a[t], bh[u][0], bh[u][2]);
                mma_fp16(acc[t][u * 2 + 1], a[t], bh[u][1], bh[u][3]);
            }
        // pass 1: A*Bl
#pragma unroll
        for (int t = 0; t < 2; t++)
#pragma unroll
            for (int u = 0; u < 4; u++) {
                mma_fp16(acc[t][u * 2], a[t], bl[u][0], bl[u][2]);
                mma_fp16(acc[t][u * 2 + 1], a[t], bl[u][1], bl[u][3]);
            }
    }
}

// ---------------- GEMM1: proj[b][p][o] = x^T @ conv_w^T + conv_b ----------------
struct PF1 {
    uint32_t a[8];
    int4 bh[2], bl[2];
};

__device__ __forceinline__ void pf1_load(PF1& f, const float* __restrict__ xb,
                                         const __half* __restrict__ wh,
                                         const __half* __restrict__ wl,
                                         int kc, int am, int ach, int tid) {
#pragma unroll
    for (int i = 0; i < 8; i++) {
        int cl = ach * 16 + i * 2;
        float v0 = xb[(size_t)(kc + cl) * HWS + am];
        float v1 = xb[(size_t)(kc + cl + 1) * HWS + am];
        __half2 h = __floats2half2_rn(v0, v1);
        f.a[i] = *reinterpret_cast<uint32_t*>(&h);
    }
#pragma unroll
    for (int j = 0; j < 2; j++) {
        int e = j * 256 + tid;
        int row = e >> 2, ch = e & 3;
        f.bh[j] = *(const int4*)(wh + (size_t)row * C + kc + ch * 8);
        f.bl[j] = *(const int4*)(wl + (size_t)row * C + kc + ch * 8);
    }
}

__device__ __forceinline__ void pf1_store(const PF1& f, char* base, int am, int ach, int tid) {
#pragma unroll
    for (int i = 0; i < 8; i++) {
        int cl = ach * 16 + i * 2;
        *(uint32_t*)(base + OFF_A + am * ROWB + cl * 2) = f.a[i];
    }
#pragma unroll
    for (int j = 0; j < 2; j++) {
        int e = j * 256 + tid;
        int row = e >> 2, ch = e & 3;
        *(int4*)(base + OFF_BH + row * ROWB + ch * 16) = f.bh[j];
        *(int4*)(base + OFF_BL + row * ROWB + ch * 16) = f.bl[j];
    }
}

__global__ __launch_bounds__(256) void gemm1_mma(const float* __restrict__ x,
                                                 const float* __restrict__ conv_b) {
    extern __shared__ char sm[];
    const uint32_t smb = smem_u32(sm);
    const int tid = threadIdx.x;
    const int wid = tid >> 5, lane = tid & 31;
    const int warp_m = wid & 3, warp_n = wid >> 2;
    const int lr = lane & 15, lc = lane >> 4;
    const int p0 = blockIdx.x * 128, o0 = blockIdx.y * 128, b = blockIdx.z;

    if (tid < 128) ((float*)(sm + OFF_BIAS))[tid] = conv_b[o0 + tid];

    const float* xb = x + (size_t)b * C * HWS + p0;
    const __half* wh = g_w1h + (size_t)o0 * C;
    const __half* wl = g_w1l + (size_t)o0 * C;
    const int am = tid & 127, ach = tid >> 7;

    float acc[2][8][4];
#pragma unroll
    for (int t = 0; t < 2; t++)
#pragma unroll
        for (int j = 0; j < 8; j++)
#pragma unroll
            for (int q = 0; q < 4; q++) acc[t][j][q] = 0.f;

    PF1 f;
    pf1_load(f, xb, wh, wl, 0, am, ach, tid);
    pf1_store(f, sm, am, ach, tid);
    __syncthreads();

    for (int kt = 0; kt < 8; kt++) {
        const int buf = kt & 1;
        if (kt < 7) pf1_load(f, xb, wh, wl, (kt + 1) * 32, am, ach, tid);
        mma_chunk(acc, smb + buf * BUFSZ, warp_m, warp_n, lr, lc);
        if (kt < 7) {
            pf1_store(f, sm + (buf ^ 1) * BUFSZ, am, ach, tid);
            __syncthreads();
        }
    }

    // epilogue: write proj [b][p][o] + bias
    const float* sbias = (const float*)(sm + OFF_BIAS);
    float* Cb = g_proj + ((size_t)b * HWS + p0) * C + o0;
    const int g4 = lane >> 2, tg = lane & 3;
#pragma unroll
    for (int t = 0; t < 2; t++) {
        const int r0 = warp_m * 32 + t * 16 + g4;
#pragma unroll
        for (int j = 0; j < 8; j++) {
            const int oc = warp_n * 64 + j * 8 + tg * 2;
            float b0 = sbias[oc], b1 = sbias[oc + 1];
            float2 v0 = make_float2(acc[t][j][0] + b0, acc[t][j][1] + b1);
            float2 v1 = make_float2(acc[t][j][2] + b0, acc[t][j][3] + b1);
            *(float2*)(Cb + (size_t)r0 * C + oc) = v0;
            *(float2*)(Cb + (size_t)(r0 + 8) * C + oc) = v1;
        }
    }
}

// ---------------- GEMM2: out[b][o][p] = feat @ w2f^T + bias2 ----------------
struct PF2 {
    int4 a[2], bh[2], bl[2];
};

__device__ __forceinline__ void pf2_load(PF2& f, const __half* __restrict__ fh,
                                         const __half* __restrict__ wh,
                                         const __half* __restrict__ wl,
                                         int kc, int tid) {
#pragma unroll
    for (int j = 0; j < 2; j++) {
        int e = j * 256 + tid;
        int row = e >> 2, ch = e & 3;
        f.a[j]  = *(const int4*)(fh + (size_t)row * C + kc + ch * 8);
        f.bh[j] = *(const int4*)(wh + (size_t)row * C + kc + ch * 8);
        f.bl[j] = *(const int4*)(wl + (size_t)row * C + kc + ch * 8);
    }
}

__device__ __forceinline__ void pf2_store(const PF2& f, char* base, int tid) {
#pragma unroll
    for (int j = 0; j < 2; j++) {
        int e = j * 256 + tid;
        int row = e >> 2, ch = e & 3;
        *(int4*)(base + OFF_A  + row * ROWB + ch * 16) = f.a[j];
        *(int4*)(base + OFF_BH + row * ROWB + ch * 16) = f.bh[j];
        *(int4*)(base + OFF_BL + row * ROWB + ch * 16) = f.bl[j];
    }
}

__global__ __launch_bounds__(256) void gemm2_mma(float* __restrict__ out) {
    extern __shared__ char sm[];
    const uint32_t smb = smem_u32(sm);
    const int tid = threadIdx.x;
    const int wid = tid >> 5, lane = tid & 31;
    const int warp_m = wid & 3, warp_n = wid >> 2;
    const int lr = lane & 15, lc = lane >> 4;
    const int p0 = blockIdx.x * 128, o0 = blockIdx.y * 128, b = blockIdx.z;

    if (tid < 128) ((float*)(sm + OFF_BIAS))[tid] = g_bias2[o0 + tid];

    const __half* fh = g_feat + ((size_t)b * HWS + p0) * C;
    const __half* wh = g_w2h + (size_t)o0 * C;
    const __half* wl = g_w2l + (size_t)o0 * C;

    float acc[2][8][4];
#pragma unroll
    for (int t = 0; t < 2; t++)
#pragma unroll
        for (int j = 0; j < 8; j++)
#pragma unroll
            for (int q = 0; q < 4; q++) acc[t][j][q] = 0.f;

    PF2 f;
    pf2_load(f, fh, wh, wl, 0, tid);
    pf2_store(f, sm, tid);
    __syncthreads();

    for (int kt = 0; kt < 8; kt++) {
        const int buf = kt & 1;
        if (kt < 7) pf2_load(f, fh, wh, wl, (kt + 1) * 32, tid);
        mma_chunk(acc, smb + buf * BUFSZ, warp_m, warp_n, lr, lc);
        if (kt < 7) {
            pf2_store(f, sm + (buf ^ 1) * BUFSZ, tid);
            __syncthreads();
        }
    }

    // epilogue: transpose through smem -> channel-major out[b][o][p]
    __syncthreads();
    float* Cs = (float*)sm;   // 128 x 33 staging
    const float* sbias = (const float*)(sm + OFF_BIAS);
    float* Ob = out + ((size_t)b * C + o0) * HWS + p0;
    const int g4 = lane >> 2, tg = lane & 3;
#pragma unroll
    for (int g = 0; g < 4; g++) {
        if (warp_n == (g >> 1)) {
#pragma unroll
            for (int t = 0; t < 2; t++)
#pragma unroll
                for (int jj = 0; jj < 4; jj++) {
                    const int j = (g & 1) * 4 + jj;
                    const int r = warp_m * 32 + t * 16 + g4;
                    const int cl = jj * 8 + tg * 2;
                    Cs[r * 33 + cl] = acc[t][j][0];
                    Cs[r * 33 + cl + 1] = acc[t][j][1];
                    Cs[(r + 8) * 33 + cl] = acc[t][j][2];
                    Cs[(r + 8) * 33 + cl + 1] = acc[t][j][3];
                }
        }
        __syncthreads();
#pragma unroll
        for (int q = 0; q < 16; q++) {
            const int e = q * 256 + tid;
            const int col = e >> 7, mm = e & 127;
            const int oc = g * 32 + col;
            Ob[(size_t)oc * HWS + mm] = Cs[mm * 33 + col] + sbias[oc];
        }
        __syncthreads();
    }
}

// ---------------- aux: flows + softmax weights -> corner indices & weights ----------------
#define ACK 32
__global__ void aux_kernel(const float* __restrict__ x,
                           const float* __restrict__ off_w, const float* __restrict__ off_b,
                           const float* __restrict__ wgt_w, const float* __restrict__ wgt_b) {
    __shared__ float wsi[C * 12];
    __shared__ float xs[ACK][256];
    const int tid = threadIdx.x;
    const int b = blockIdx.y;
    const int p0 = blockIdx.x * 256;

    for (int e = tid; e < 2 * C * KB; e += 128) {
        int kd = e >> 8;
        int c = e & 255;
        wsi[c * 12 + kd] = off_w[e];
    }
    for (int e = tid; e < C * KB; e += 128) {
        int k = e >> 8, c = e & 255;
        wsi[c * 12 + 8 + k] = wgt_w[e];
    }

    float acc0[12], acc1[12];
#pragma unroll
    for (int j = 0; j < 12; j++) { acc0[j] = 0.f; acc1[j] = 0.f; }

    const float* xb = x + (size_t)b * C * HWS;
    for (int cc = 0; cc < C; cc += ACK) {
        __syncthreads();
        for (int e4 = tid; e4 < ACK * 64; e4 += 128) {
            int r = e4 >> 6;
            int p4 = (e4 & 63) * 4;
            *(float4*)&xs[r][p4] = *(const float4*)(xb + (size_t)(cc + r) * HWS + p0 + p4);
        }
        __syncthreads();
#pragma unroll 4
        for (int r = 0; r < ACK; r++) {
            float xv0 = xs[r][tid];
            float xv1 = xs[r][tid + 128];
            const float4* wp = (const float4*)(wsi + (cc + r) * 12);
            float4 wa = wp[0], wb = wp[1], wc = wp[2];
            float w[12] = {wa.x, wa.y, wa.z, wa.w, wb.x, wb.y, wb.z, wb.w,
                           wc.x, wc.y, wc.z, wc.w};
#pragma unroll
            for (int j = 0; j < 12; j++) {
                acc0[j] = fmaf(xv0, w[j], acc0[j]);
                acc1[j] = fmaf(xv1, w[j], acc1[j]);
            }
        }
    }

    for (int half = 0; half < 2; half++) {
        float* a = half ? acc1 : acc0;
        int p = p0 + tid + half * 128;
        int py = p >> 7, px = p & 127;
        float l0 = a[8] + wgt_b[0], l1 = a[9] + wgt_b[1];
        float l2 = a[10] + wgt_b[2], l3 = a[11] + wgt_b[3];
        float mx = fmaxf(fmaxf(l0, l1), fmaxf(l2, l3));
        float e0 = __expf(l0 - mx), e1 = __expf(l1 - mx);
        float e2 = __expf(l2 - mx), e3 = __expf(l3 - mx);
        float invs = 1.f / (e0 + e1 + e2 + e3);
        float wk4[4] = {e0 * invs, e1 * invs, e2 * invs, e3 * invs};
#pragma unroll
        for (int k = 0; k < KB; k++) {
            float vx = (float)px + a[2 * k] + off_b[2 * k];
            float vy = (float)py + a[2 * k + 1] + off_b[2 * k + 1];
            float x0f = floorf(vx), y0f = floorf(vy);
            float wx1 = vx - x0f, wy1 = vy - y0f;
            int x0 = (int)x0f, y0 = (int)y0f;
            bool vx0 = (x0 >= 0) && (x0 <= WW - 1);
            bool vx1 = (x0 + 1 >= 0) && (x0 + 1 <= WW - 1);
            bool vy0 = (y0 >= 0) && (y0 <= HH - 1);
            bool vy1 = (y0 + 1 >= 0) && (y0 + 1 <= HH - 1);
            float wk = wk4[k];
            float w00 = (1.f - wx1) * (1.f - wy1) * wk * (float)(vx0 && vy0);
            float w01 = wx1 * (1.f - wy1) * wk * (float)(vx1 && vy0);
            float w10 = (1.f - wx1) * wy1 * wk * (float)(vx0 && vy1);
            float w11 = wx1 * wy1 * wk * (float)(vx1 && vy1);
            int xc0 = min(max(x0, 0), WW - 1);
            int xc1 = min(max(x0 + 1, 0), WW - 1);
            int yc0 = min(max(y0, 0), HH - 1);
            int yc1 = min(max(y0 + 1, 0), HH - 1);
            size_t off = ((size_t)(b * KB + k)) * HWS + p;
            g_idx[off] = make_int4(yc0 * WW + xc0, yc0 * WW + xc1,
                                   yc1 * WW + xc0, yc1 * WW + xc1);
            g_cw[off] = make_float4(w00, w01, w10, w11);
        }
    }
}

// ---------------- sampling: feat = proj + weighted gather; emit fp16 ----------------
__global__ void sample_kernel() {
    const int warp = threadIdx.x >> 5;
    const int lane = threadIdx.x & 31;
    const size_t pp = (size_t)blockIdx.x * 8 + warp;
    const int b = (int)(pp >> 14);
    const int p = (int)(pp & 16383);

    const float4* projb = (const float4*)g_proj + (size_t)b * HWS * 64;
    const float4* self = projb + (size_t)p * 64;
    float4 aL = self[lane];
    float4 aH = self[32 + lane];

    const size_t kb = (size_t)b * KB * HWS + p;
#pragma unroll
    for (int k = 0; k < KB; k++) {
        int4 id = g_idx[kb + (size_t)k * HWS];
        float4 w = g_cw[kb + (size_t)k * HWS];
        const float4* r0 = projb + (size_t)id.x * 64;
        const float4* r1 = projb + (size_t)id.y * 64;
        const float4* r2 = projb + (size_t)id.z * 64;
        const float4* r3 = projb + (size_t)id.w * 64;
        float4 v;
        v = r0[lane];      aL.x = fmaf(w.x, v.x, aL.x); aL.y = fmaf(w.x, v.y, aL.y); aL.z = fmaf(w.x, v.z, aL.z); aL.w = fmaf(w.x, v.w, aL.w);
        v = r0[32 + lane]; aH.x = fmaf(w.x, v.x, aH.x); aH.y = fmaf(w.x, v.y, aH.y); aH.z = fmaf(w.x, v.z, aH.z); aH.w = fmaf(w.x, v.w, aH.w);
        v = r1[lane];      aL.x = fmaf(w.y, v.x, aL.x); aL.y = fmaf(w.y, v.y, aL.y); aL.z = fmaf(w.y, v.z, aL.z); aL.w = fmaf(w.y, v.w, aL.w);
        v = r1[32 + lane]; aH.x = fmaf(w.y, v.x, aH.x); aH.y = fmaf(w.y, v.y, aH.y); aH.z = fmaf(w.y, v.z, aH.z); aH.w = fmaf(w.y, v.w, aH.w);
        v = r2[lane];      aL.x = fmaf(w.z, v.x, aL.x); aL.y = fmaf(w.z, v.y, aL.y); aL.z = fmaf(w.z, v.z, aL.z); aL.w = fmaf(w.z, v.w, aL.w);
        v = r2[32 + lane]; aH.x = fmaf(w.z, v.x, aH.x); aH.y = fmaf(w.z, v.y, aH.y); aH.z = fmaf(w.z, v.z, aH.z); aH.w = fmaf(w.z, v.w, aH.w);
        v = r3[lane];      aL.x = fmaf(w.w, v.x, aL.x); aL.y = fmaf(w.w, v.y, aL.y); aL.z = fmaf(w.w, v.z, aL.z); aL.w = fmaf(w.w, v.w, aL.w);
        v = r3[32 + lane]; aH.x = fmaf(w.w, v.x, aH.x); aH.y = fmaf(w.w, v.y, aH.y); aH.z = fmaf(w.w, v.z, aH.z); aH.w = fmaf(w.w, v.w, aH.w);
    }
    const size_t base = ((size_t)b * HWS + p) * C;
    __half2 h0 = __floats2half2_rn(aL.x, aL.y);
    __half2 h1 = __floats2half2_rn(aL.z, aL.w);
    *(uint2*)&g_feat[base + lane * 4] =
        make_uint2(*reinterpret_cast<uint32_t*>(&h0), *reinterpret_cast<uint32_t*>(&h1));
    h0 = __floats2half2_rn(aH.x, aH.y);
    h1 = __floats2half2_rn(aH.z, aH.w);
    *(uint2*)&g_feat[base + 128 + lane * 4] =
        make_uint2(*reinterpret_cast<uint32_t*>(&h0), *reinterpret_cast<uint32_t*>(&h1));
}

// ---------------- launch ----------------
extern "C" void kernel_launch(void* const* d_in, const int* in_sizes, int n_in,
                              void* d_out, int out_size) {
    (void)in_sizes; (void)n_in; (void)out_size;
    const float* x      = (const float*)d_in[0];
    const float* conv_w = (const float*)d_in[1];
    const float* conv_b = (const float*)d_in[2];
    const float* off_w  = (const float*)d_in[3];
    const float* off_b  = (const float*)d_in[4];
    const float* wgt_w  = (const float*)d_in[5];
    const float* wgt_b  = (const float*)d_in[6];
    const float* gamma  = (const float*)d_in[7];
    const float* beta   = (const float*)d_in[8];
    const float* rmean  = (const float*)d_in[9];
    const float* rvar   = (const float*)d_in[10];
    const float* out_w  = (const float*)d_in[11];
    const float* out_b  = (const float*)d_in[12];
    float* out = (float*)d_out;

    static bool attr_done = false;
    if (!attr_done) {
        cudaFuncSetAttribute(gemm1_mma, cudaFuncAttributeMaxDynamicSharedMemorySize, GEMM_SMEM);
        cudaFuncSetAttribute(gemm2_mma, cudaFuncAttributeMaxDynamicSharedMemorySize, GEMM_SMEM);
        attr_done = true;
    }

    prep_kernel<<<C, C>>>(conv_w, out_w, out_b, gamma, beta, rmean, rvar);
    gemm1_mma<<<dim3(HWS / 128, C / 128, BATCH), 256, GEMM_SMEM>>>(x, conv_b);
    aux_kernel<<<dim3(HWS / 256, BATCH), 128>>>(x, off_w, off_b, wgt_w, wgt_b);
    sample_kernel<<<NPX / 8, 256>>>();
    gemm2_mma<<<dim3(HWS / 128, C / 128, BATCH), 256, GEMM_SMEM>>>(out);
}

// round 5
// speedup vs baseline: 2.3818x; 1.0844x over previous
#include <cuda_runtime.h>
#include <cuda_fp16.h>
#include <cstdint>

// Problem constants
#define BATCH 8
#define C 256
#define KB 4
#define HH 128
#define WW 128
#define HWS 16384
#define NPX (BATCH*HWS)

// ---------------- device scratch ----------------
__device__ __align__(16) __half g_projh[(size_t)NPX * C]; // proj fp16 [b][p][c]
__device__ __align__(16) __half g_feat[(size_t)NPX * C];  // feat fp16 [b][p][c]
__device__ __align__(16) __half g_w1h[C * C];             // conv_w hi fp16 [o][c]
__device__ __align__(16) __half g_w1l[C * C];             // conv_w lo fp16
__device__ __align__(16) __half g_w2h[C * C];             // BN-folded out_w hi [o][c]
__device__ __align__(16) __half g_w2l[C * C];
__device__ float g_bias2[C];
__device__ float4 g_cw[(size_t)BATCH * KB * HWS];
__device__ int4   g_idx[(size_t)BATCH * KB * HWS];

// ---------------- helpers ----------------
__device__ __forceinline__ uint32_t smem_u32(const void* p) {
    uint32_t a;
    asm("{ .reg .u64 t; cvta.to.shared.u64 t, %1; cvt.u32.u64 %0, t; }" : "=r"(a) : "l"(p));
    return a;
}

__device__ __forceinline__ void ldsm4(uint32_t* r, uint32_t addr) {
    asm volatile("ldmatrix.sync.aligned.m8n8.x4.shared.b16 {%0,%1,%2,%3}, [%4];"
                 : "=r"(r[0]), "=r"(r[1]), "=r"(r[2]), "=r"(r[3]) : "r"(addr));
}

__device__ __forceinline__ void mma_fp16(float* d, const uint32_t* a, uint32_t b0, uint32_t b1) {
    asm volatile(
        "mma.sync.aligned.m16n8k16.row.col.f32.f16.f16.f32 "
        "{%0,%1,%2,%3}, {%4,%5,%6,%7}, {%8,%9}, {%0,%1,%2,%3};"
        : "+f"(d[0]), "+f"(d[1]), "+f"(d[2]), "+f"(d[3])
        : "r"(a[0]), "r"(a[1]), "r"(a[2]), "r"(a[3]), "r"(b0), "r"(b1));
}

// SMEM tile geometry: 128 rows x 32 fp16, row stride 80B (64B data + 16B pad)
#define ROWB 80
#define TSZ  (128 * ROWB)          // 10240 per tile
#define BUFSZ (3 * TSZ)            // A, BH, BL per buffer = 30720
#define OFF_A  0
#define OFF_BH TSZ
#define OFF_BL (2 * TSZ)
#define OFF_BIAS (2 * BUFSZ)       // 61440
#define GEMM_SMEM (OFF_BIAS + 1024)

// ---------------- prep: split weights to fp16 hi/lo, fold BN ----------------
__global__ void prep_kernel(const float* __restrict__ conv_w,
                            const float* __restrict__ out_w, const float* __restrict__ out_b,
                            const float* __restrict__ gamma, const float* __restrict__ beta,
                            const float* __restrict__ rmean, const float* __restrict__ rvar) {
    int o = blockIdx.x;
    int c = threadIdx.x;
    __shared__ float red[C];
    float w1 = conv_w[o * C + c];
    __half h1 = __float2half_rn(w1);
    g_w1h[o * C + c] = h1;
    g_w1l[o * C + c] = __float2half_rn(w1 - __half2float(h1));

    float inv = gamma[c] / sqrtf(rvar[c] + 1e-5f);
    float w = out_w[o * C + c];
    float w2 = w * inv;
    __half h2 = __float2half_rn(w2);
    g_w2h[o * C + c] = h2;
    g_w2l[o * C + c] = __float2half_rn(w2 - __half2float(h2));

    red[c] = w * (beta[c] - rmean[c] * inv);
    __syncthreads();
    for (int s = 128; s > 0; s >>= 1) {
        if (c < s) red[c] += red[c + s];
        __syncthreads();
    }
    if (c == 0) g_bias2[o] = red[0] + out_b[o];
}

// ---------------- shared mma tile step (2-pass: A * (Bh + Bl)) ----------------
__device__ __forceinline__ void mma_chunk(float acc[2][8][4], uint32_t smbuf,
                                          int warp_m, int warp_n, int lr, int lc) {
    const uint32_t a_base = smbuf + OFF_A + (uint32_t)(warp_m * 32 + lr) * ROWB + lc * 16;
    const uint32_t b_base = smbuf + OFF_BH + (uint32_t)(warp_n * 64 + lr) * ROWB + lc * 16;
#pragma unroll
    for (int s = 0; s < 2; s++) {
        uint32_t a[2][4];
        uint32_t bh[4][4], bl[4][4];
#pragma unroll
        for (int t = 0; t < 2; t++)
            ldsm4(a[t], a_base + t * (16 * ROWB) + s * 32);
#pragma unroll
        for (int u = 0; u < 4; u++) {
            ldsm4(bh[u], b_base + u * (16 * ROWB) + s * 32);
            ldsm4(bl[u], b_base + TSZ + u * (16 * ROWB) + s * 32);
        }
#pragma unroll
        for (int t = 0; t < 2; t++)
#pragma unroll
            for (int u = 0; u < 4; u++) {
                mma_fp16(acc[t][u * 2], a[t], bh[u][0], bh[u][2]);
                mma_fp16(acc[t][u * 2 + 1], a[t], bh[u][1], bh[u][3]);
            }
#pragma unroll
        for (int t = 0; t < 2; t++)
#pragma unroll
            for (int u = 0; u < 4; u++) {
                mma_fp16(acc[t][u * 2], a[t], bl[u][0], bl[u][2]);
                mma_fp16(acc[t][u * 2 + 1], a[t], bl[u][1], bl[u][3]);
            }
    }
}

// ---------------- GEMM1: proj[b][p][o] = x^T @ conv_w^T + conv_b ----------------
struct PF1 {
    uint32_t a[8];
    int4 bh[2], bl[2];
};

__device__ __forceinline__ void pf1_load(PF1& f, const float* __restrict__ xb,
                                         const __half* __restrict__ wh,
                                         const __half* __restrict__ wl,
                                         int kc, int am, int ach, int tid) {
#pragma unroll
    for (int i = 0; i < 8; i++) {
        int cl = ach * 16 + i * 2;
        float v0 = xb[(size_t)(kc + cl) * HWS + am];
        float v1 = xb[(size_t)(kc + cl + 1) * HWS + am];
        __half2 h = __floats2half2_rn(v0, v1);
        f.a[i] = *reinterpret_cast<uint32_t*>(&h);
    }
#pragma unroll
    for (int j = 0; j < 2; j++) {
        int e = j * 256 + tid;
        int row = e >> 2, ch = e & 3;
        f.bh[j] = *(const int4*)(wh + (size_t)row * C + kc + ch * 8);
        f.bl[j] = *(const int4*)(wl + (size_t)row * C + kc + ch * 8);
    }
}

__device__ __forceinline__ void pf1_store(const PF1& f, char* base, int am, int ach, int tid) {
#pragma unroll
    for (int i = 0; i < 8; i++) {
        int cl = ach * 16 + i * 2;
        *(uint32_t*)(base + OFF_A + am * ROWB + cl * 2) = f.a[i];
    }
#pragma unroll
    for (int j = 0; j < 2; j++) {
        int e = j * 256 + tid;
        int row = e >> 2, ch = e & 3;
        *(int4*)(base + OFF_BH + row * ROWB + ch * 16) = f.bh[j];
        *(int4*)(base + OFF_BL + row * ROWB + ch * 16) = f.bl[j];
    }
}

__global__ __launch_bounds__(256) void gemm1_mma(const float* __restrict__ x,
                                                 const float* __restrict__ conv_b) {
    extern __shared__ char sm[];
    const uint32_t smb = smem_u32(sm);
    const int tid = threadIdx.x;
    const int wid = tid >> 5, lane = tid & 31;
    const int warp_m = wid & 3, warp_n = wid >> 2;
    const int lr = lane & 15, lc = lane >> 4;
    const int p0 = blockIdx.x * 128, o0 = blockIdx.y * 128, b = blockIdx.z;

    if (tid < 128) ((float*)(sm + OFF_BIAS))[tid] = conv_b[o0 + tid];

    const float* xb = x + (size_t)b * C * HWS + p0;
    const __half* wh = g_w1h + (size_t)o0 * C;
    const __half* wl = g_w1l + (size_t)o0 * C;
    const int am = tid & 127, ach = tid >> 7;

    float acc[2][8][4];
#pragma unroll
    for (int t = 0; t < 2; t++)
#pragma unroll
        for (int j = 0; j < 8; j++)
#pragma unroll
            for (int q = 0; q < 4; q++) acc[t][j][q] = 0.f;

    PF1 f;
    pf1_load(f, xb, wh, wl, 0, am, ach, tid);
    pf1_store(f, sm, am, ach, tid);
    __syncthreads();

    for (int kt = 0; kt < 8; kt++) {
        const int buf = kt & 1;
        if (kt < 7) pf1_load(f, xb, wh, wl, (kt + 1) * 32, am, ach, tid);
        mma_chunk(acc, smb + buf * BUFSZ, warp_m, warp_n, lr, lc);
        if (kt < 7) {
            pf1_store(f, sm + (buf ^ 1) * BUFSZ, am, ach, tid);
            __syncthreads();
        }
    }

    // epilogue: write proj fp16 [b][p][o] + bias
    const float* sbias = (const float*)(sm + OFF_BIAS);
    __half* Cb = g_projh + ((size_t)b * HWS + p0) * C + o0;
    const int g4 = lane >> 2, tg = lane & 3;
#pragma unroll
    for (int t = 0; t < 2; t++) {
        const int r0 = warp_m * 32 + t * 16 + g4;
#pragma unroll
        for (int j = 0; j < 8; j++) {
            const int oc = warp_n * 64 + j * 8 + tg * 2;
            float b0 = sbias[oc], b1 = sbias[oc + 1];
            __half2 v0 = __floats2half2_rn(acc[t][j][0] + b0, acc[t][j][1] + b1);
            __half2 v1 = __floats2half2_rn(acc[t][j][2] + b0, acc[t][j][3] + b1);
            *(uint32_t*)(Cb + (size_t)r0 * C + oc) = *reinterpret_cast<uint32_t*>(&v0);
            *(uint32_t*)(Cb + (size_t)(r0 + 8) * C + oc) = *reinterpret_cast<uint32_t*>(&v1);
        }
    }
}

// ---------------- GEMM2: out[b][o][p] = feat @ w2f^T + bias2 ----------------
struct PF2 {
    int4 a[2], bh[2], bl[2];
};

__device__ __forceinline__ void pf2_load(PF2& f, const __half* __restrict__ fh,
                                         const __half* __restrict__ wh,
                                         const __half* __restrict__ wl,
                                         int kc, int tid) {
#pragma unroll
    for (int j = 0; j < 2; j++) {
        int e = j * 256 + tid;
        int row = e >> 2, ch = e & 3;
        f.a[j]  = *(const int4*)(fh + (size_t)row * C + kc + ch * 8);
        f.bh[j] = *(const int4*)(wh + (size_t)row * C + kc + ch * 8);
        f.bl[j] = *(const int4*)(wl + (size_t)row * C + kc + ch * 8);
    }
}

__device__ __forceinline__ void pf2_store(const PF2& f, char* base, int tid) {
#pragma unroll
    for (int j = 0; j < 2; j++) {
        int e = j * 256 + tid;
        int row = e >> 2, ch = e & 3;
        *(int4*)(base + OFF_A  + row * ROWB + ch * 16) = f.a[j];
        *(int4*)(base + OFF_BH + row * ROWB + ch * 16) = f.bh[j];
        *(int4*)(base + OFF_BL + row * ROWB + ch * 16) = f.bl[j];
    }
}

__global__ __launch_bounds__(256) void gemm2_mma(float* __restrict__ out) {
    extern __shared__ char sm[];
    const uint32_t smb = smem_u32(sm);
    const int tid = threadIdx.x;
    const int wid = tid >> 5, lane = tid & 31;
    const int warp_m = wid & 3, warp_n = wid >> 2;
    const int lr = lane & 15, lc = lane >> 4;
    const int p0 = blockIdx.x * 128, o0 = blockIdx.y * 128, b = blockIdx.z;

    if (tid < 128) ((float*)(sm + OFF_BIAS))[tid] = g_bias2[o0 + tid];

    const __half* fh = g_feat + ((size_t)b * HWS + p0) * C;
    const __half* wh = g_w2h + (size_t)o0 * C;
    const __half* wl = g_w2l + (size_t)o0 * C;

    float acc[2][8][4];
#pragma unroll
    for (int t = 0; t < 2; t++)
#pragma unroll
        for (int j = 0; j < 8; j++)
#pragma unroll
            for (int q = 0; q < 4; q++) acc[t][j][q] = 0.f;

    PF2 f;
    pf2_load(f, fh, wh, wl, 0, tid);
    pf2_store(f, sm, tid);
    __syncthreads();

    for (int kt = 0; kt < 8; kt++) {
        const int buf = kt & 1;
        if (kt < 7) pf2_load(f, fh, wh, wl, (kt + 1) * 32, tid);
        mma_chunk(acc, smb + buf * BUFSZ, warp_m, warp_n, lr, lc);
        if (kt < 7) {
            pf2_store(f, sm + (buf ^ 1) * BUFSZ, tid);
            __syncthreads();
        }
    }

    // epilogue: transpose through smem -> channel-major out[b][o][p]
    __syncthreads();
    float* Cs = (float*)sm;   // 128 x 33 staging
    const float* sbias = (const float*)(sm + OFF_BIAS);
    float* Ob = out + ((size_t)b * C + o0) * HWS + p0;
    const int g4 = lane >> 2, tg = lane & 3;
#pragma unroll
    for (int g = 0; g < 4; g++) {
        if (warp_n == (g >> 1)) {
#pragma unroll
            for (int t = 0; t < 2; t++)
#pragma unroll
                for (int jj = 0; jj < 4; jj++) {
                    const int j = (g & 1) * 4 + jj;
                    const int r = warp_m * 32 + t * 16 + g4;
                    const int cl = jj * 8 + tg * 2;
                    Cs[r * 33 + cl] = acc[t][j][0];
                    Cs[r * 33 + cl + 1] = acc[t][j][1];
                    Cs[(r + 8) * 33 + cl] = acc[t][j][2];
                    Cs[(r + 8) * 33 + cl + 1] = acc[t][j][3];
                }
        }
        __syncthreads();
#pragma unroll
        for (int q = 0; q < 16; q++) {
            const int e = q * 256 + tid;
            const int col = e >> 7, mm = e & 127;
            const int oc = g * 32 + col;
            Ob[(size_t)oc * HWS + mm] = Cs[mm * 33 + col] + sbias[oc];
        }
        __syncthreads();
    }
}

// ---------------- aux: direct-global GEMV, 1 px/thread ----------------
__global__ __launch_bounds__(256) void aux_kernel(
        const float* __restrict__ x,
        const float* __restrict__ off_w, const float* __restrict__ off_b,
        const float* __restrict__ wgt_w, const float* __restrict__ wgt_b) {
    __shared__ float wsi[C * 12];      // interleaved [c][12]
    const int tid = threadIdx.x;
    const int pp = blockIdx.x * 256 + tid;
    const int b = pp >> 14;
    const int p = pp & 16383;

    for (int e = tid; e < 2 * C * KB; e += 256) {      // off_w: [(k*2+d)][c]
        int kd = e >> 8, c = e & 255;
        wsi[c * 12 + kd] = off_w[e];
    }
    for (int e = tid; e < C * KB; e += 256) {          // wgt_w: [k][c]
        int k = e >> 8, c = e & 255;
        wsi[c * 12 + 8 + k] = wgt_w[e];
    }
    __syncthreads();

    float acc[12];
#pragma unroll
    for (int j = 0; j < 12; j++) acc[j] = 0.f;

    const float* xb = x + (size_t)b * C * HWS + p;
#pragma unroll 4
    for (int c = 0; c < C; c++) {
        float xv = xb[(size_t)c * HWS];
        const float4* wp = (const float4*)(wsi + c * 12);
        float4 wa = wp[0], wb = wp[1], wc = wp[2];
        acc[0] = fmaf(xv, wa.x, acc[0]);  acc[1] = fmaf(xv, wa.y, acc[1]);
        acc[2] = fmaf(xv, wa.z, acc[2]);  acc[3] = fmaf(xv, wa.w, acc[3]);
        acc[4] = fmaf(xv, wb.x, acc[4]);  acc[5] = fmaf(xv, wb.y, acc[5]);
        acc[6] = fmaf(xv, wb.z, acc[6]);  acc[7] = fmaf(xv, wb.w, acc[7]);
        acc[8] = fmaf(xv, wc.x, acc[8]);  acc[9] = fmaf(xv, wc.y, acc[9]);
        acc[10] = fmaf(xv, wc.z, acc[10]); acc[11] = fmaf(xv, wc.w, acc[11]);
    }

    const int py = p >> 7, px = p & 127;
    // softmax over 4 logits
    float l0 = acc[8] + wgt_b[0], l1 = acc[9] + wgt_b[1];
    float l2 = acc[10] + wgt_b[2], l3 = acc[11] + wgt_b[3];
    float mx = fmaxf(fmaxf(l0, l1), fmaxf(l2, l3));
    float e0 = __expf(l0 - mx), e1 = __expf(l1 - mx);
    float e2 = __expf(l2 - mx), e3 = __expf(l3 - mx);
    float invs = 1.f / (e0 + e1 + e2 + e3);
    float wk4[4] = {e0 * invs, e1 * invs, e2 * invs, e3 * invs};
#pragma unroll
    for (int k = 0; k < KB; k++) {
        float vx = (float)px + acc[2 * k] + off_b[2 * k];
        float vy = (float)py + acc[2 * k + 1] + off_b[2 * k + 1];
        float x0f = floorf(vx), y0f = floorf(vy);
        float wx1 = vx - x0f, wy1 = vy - y0f;
        int x0 = (int)x0f, y0 = (int)y0f;
        bool vx0 = (x0 >= 0) && (x0 <= WW - 1);
        bool vx1 = (x0 + 1 >= 0) && (x0 + 1 <= WW - 1);
        bool vy0 = (y0 >= 0) && (y0 <= HH - 1);
        bool vy1 = (y0 + 1 >= 0) && (y0 + 1 <= HH - 1);
        float wk = wk4[k];
        float w00 = (1.f - wx1) * (1.f - wy1) * wk * (float)(vx0 && vy0);
        float w01 = wx1 * (1.f - wy1) * wk * (float)(vx1 && vy0);
        float w10 = (1.f - wx1) * wy1 * wk * (float)(vx0 && vy1);
        float w11 = wx1 * wy1 * wk * (float)(vx1 && vy1);
        int xc0 = min(max(x0, 0), WW - 1);
        int xc1 = min(max(x0 + 1, 0), WW - 1);
        int yc0 = min(max(y0, 0), HH - 1);
        int yc1 = min(max(y0 + 1, 0), HH - 1);
        size_t off = ((size_t)(b * KB + k)) * HWS + p;
        g_idx[off] = make_int4(yc0 * WW + xc0, yc0 * WW + xc1,
                               yc1 * WW + xc0, yc1 * WW + xc1);
        g_cw[off] = make_float4(w00, w01, w10, w11);
    }
}

// ---------------- sampling: feat = proj + weighted gather (fp16 proj) ----------------
__device__ __forceinline__ void acc_row(float* acc, uint4 v, float w) {
    const __half2* h = reinterpret_cast<const __half2*>(&v);
#pragma unroll
    for (int i = 0; i < 4; i++) {
        float2 f = __half22float2(h[i]);
        acc[2 * i]     = fmaf(w, f.x, acc[2 * i]);
        acc[2 * i + 1] = fmaf(w, f.y, acc[2 * i + 1]);
    }
}

__global__ void sample_kernel() {
    const int warp = threadIdx.x >> 5;
    const int lane = threadIdx.x & 31;
    const size_t pp = (size_t)blockIdx.x * 8 + warp;
    const int b = (int)(pp >> 14);
    const int p = (int)(pp & 16383);

    const uint4* projb = (const uint4*)g_projh + (size_t)b * HWS * 32;  // 32 uint4/row
    float acc[8];
    {
        uint4 sv = projb[(size_t)p * 32 + lane];
        const __half2* h = reinterpret_cast<const __half2*>(&sv);
#pragma unroll
        for (int i = 0; i < 4; i++) {
            float2 f = __half22float2(h[i]);
            acc[2 * i] = f.x;
            acc[2 * i + 1] = f.y;
        }
    }

    const size_t kb = (size_t)b * KB * HWS + p;
#pragma unroll
    for (int k = 0; k < KB; k++) {
        int4 id = g_idx[kb + (size_t)k * HWS];
        float4 w = g_cw[kb + (size_t)k * HWS];
        uint4 v0 = projb[(size_t)id.x * 32 + lane];
        uint4 v1 = projb[(size_t)id.y * 32 + lane];
        uint4 v2 = projb[(size_t)id.z * 32 + lane];
        uint4 v3 = projb[(size_t)id.w * 32 + lane];
        acc_row(acc, v0, w.x);
        acc_row(acc, v1, w.y);
        acc_row(acc, v2, w.z);
        acc_row(acc, v3, w.w);
    }

    __half2 o[4];
#pragma unroll
    for (int i = 0; i < 4; i++)
        o[i] = __floats2half2_rn(acc[2 * i], acc[2 * i + 1]);
    ((uint4*)g_feat)[((size_t)b * HWS + p) * 32 + lane] = *reinterpret_cast<uint4*>(o);
}

// ---------------- launch ----------------
extern "C" void kernel_launch(void* const* d_in, const int* in_sizes, int n_in,
                              void* d_out, int out_size) {
    (void)in_sizes; (void)n_in; (void)out_size;
    const float* x      = (const float*)d_in[0];
    const float* conv_w = (const float*)d_in[1];
    const float* conv_b = (const float*)d_in[2];
    const float* off_w  = (const float*)d_in[3];
    const float* off_b  = (const float*)d_in[4];
    const float* wgt_w  = (const float*)d_in[5];
    const float* wgt_b  = (const float*)d_in[6];
    const float* gamma  = (const float*)d_in[7];
    const float* beta   = (const float*)d_in[8];
    const float* rmean  = (const float*)d_in[9];
    const float* rvar   = (const float*)d_in[10];
    const float* out_w  = (const float*)d_in[11];
    const float* out_b  = (const float*)d_in[12];
    float* out = (float*)d_out;

    static bool attr_done = false;
    if (!attr_done) {
        cudaFuncSetAttribute(gemm1_mma, cudaFuncAttributeMaxDynamicSharedMemorySize, GEMM_SMEM);
        cudaFuncSetAttribute(gemm2_mma, cudaFuncAttributeMaxDynamicSharedMemorySize, GEMM_SMEM);
        attr_done = true;
    }

    prep_kernel<<<C, C>>>(conv_w, out_w, out_b, gamma, beta, rmean, rvar);
    gemm1_mma<<<dim3(HWS / 128, C / 128, BATCH), 256, GEMM_SMEM>>>(x, conv_b);
    aux_kernel<<<NPX / 256, 256>>>(x, off_w, off_b, wgt_w, wgt_b);
    sample_kernel<<<NPX / 8, 256>>>();
    gemm2_mma<<<dim3(HWS / 128, C / 128, BATCH), 256, GEMM_SMEM>>>(out);
}

// round 6
// speedup vs baseline: 2.7912x; 1.1719x over previous
#include <cuda_runtime.h>
#include <cuda_fp16.h>
#include <cstdint>

// Problem constants
#define BATCH 8
#define C 256
#define KB 4
#define HH 128
#define WW 128
#define HWS 16384
#define NPX (BATCH*HWS)

// ---------------- device scratch ----------------
__device__ __align__(16) __half g_projh[(size_t)NPX * C]; // proj fp16 [b][p][c]
__device__ __align__(16) __half g_feat[(size_t)NPX * C];  // feat fp16 [b][p][c]
__device__ __align__(16) __half g_w1[C * C];              // conv_w fp16 [o][c]
__device__ __align__(16) __half g_w2[C * C];              // BN-folded out_w fp16 [o][c]
__device__ float g_bias2[C];
__device__ float4 g_cw[(size_t)BATCH * KB * HWS];
__device__ int4   g_idx[(size_t)BATCH * KB * HWS];

// ---------------- helpers ----------------
__device__ __forceinline__ uint32_t smem_u32(const void* p) {
    uint32_t a;
    asm("{ .reg .u64 t; cvta.to.shared.u64 t, %1; cvt.u32.u64 %0, t; }" : "=r"(a) : "l"(p));
    return a;
}

__device__ __forceinline__ void ldsm4(uint32_t* r, uint32_t addr) {
    asm volatile("ldmatrix.sync.aligned.m8n8.x4.shared.b16 {%0,%1,%2,%3}, [%4];"
                 : "=r"(r[0]), "=r"(r[1]), "=r"(r[2]), "=r"(r[3]) : "r"(addr));
}

__device__ __forceinline__ void mma_fp16(float* d, const uint32_t* a, uint32_t b0, uint32_t b1) {
    asm volatile(
        "mma.sync.aligned.m16n8k16.row.col.f32.f16.f16.f32 "
        "{%0,%1,%2,%3}, {%4,%5,%6,%7}, {%8,%9}, {%0,%1,%2,%3};"
        : "+f"(d[0]), "+f"(d[1]), "+f"(d[2]), "+f"(d[3])
        : "r"(a[0]), "r"(a[1]), "r"(a[2]), "r"(a[3]), "r"(b0), "r"(b1));
}

// SMEM tile geometry: 128 rows x 32 fp16, row stride 80B (64B data + 16B pad)
#define ROWB 80
#define TSZ  (128 * ROWB)          // 10240 per tile
#define BUFSZ (2 * TSZ)            // A, B per buffer = 20480
#define OFF_A  0
#define OFF_B  TSZ
#define OFF_BIAS (2 * BUFSZ)       // 40960
#define GEMM_SMEM (OFF_BIAS + 1024)

// ---------------- prep: weights to fp16, fold BN ----------------
__global__ void prep_kernel(const float* __restrict__ conv_w,
                            const float* __restrict__ out_w, const float* __restrict__ out_b,
                            const float* __restrict__ gamma, const float* __restrict__ beta,
                            const float* __restrict__ rmean, const float* __restrict__ rvar) {
    int o = blockIdx.x;
    int c = threadIdx.x;
    __shared__ float red[C];
    g_w1[o * C + c] = __float2half_rn(conv_w[o * C + c]);

    float inv = gamma[c] / sqrtf(rvar[c] + 1e-5f);
    float w = out_w[o * C + c];
    g_w2[o * C + c] = __float2half_rn(w * inv);

    red[c] = w * (beta[c] - rmean[c] * inv);
    __syncthreads();
    for (int s = 128; s > 0; s >>= 1) {
        if (c < s) red[c] += red[c + s];
        __syncthreads();
    }
    if (c == 0) g_bias2[o] = red[0] + out_b[o];
}

// ---------------- shared mma tile step (single pass A*B) ----------------
__device__ __forceinline__ void mma_chunk(float acc[2][8][4], uint32_t smbuf,
                                          int warp_m, int warp_n, int lr, int lc) {
    const uint32_t a_base = smbuf + OFF_A + (uint32_t)(warp_m * 32 + lr) * ROWB + lc * 16;
    const uint32_t b_base = smbuf + OFF_B + (uint32_t)(warp_n * 64 + lr) * ROWB + lc * 16;
#pragma unroll
    for (int s = 0; s < 2; s++) {
        uint32_t a[2][4];
        uint32_t bb[4][4];
#pragma unroll
        for (int t = 0; t < 2; t++)
            ldsm4(a[t], a_base + t * (16 * ROWB) + s * 32);
#pragma unroll
        for (int u = 0; u < 4; u++)
            ldsm4(bb[u], b_base + u * (16 * ROWB) + s * 32);
#pragma unroll
        for (int t = 0; t < 2; t++)
#pragma unroll
            for (int u = 0; u < 4; u++) {
                mma_fp16(acc[t][u * 2], a[t], bb[u][0], bb[u][2]);
                mma_fp16(acc[t][u * 2 + 1], a[t], bb[u][1], bb[u][3]);
            }
    }
}

// ---------------- GEMM1: proj[b][p][o] = x^T @ conv_w^T + conv_b ----------------
struct PF1 {
    uint32_t a[8];
    int4 b[2];
};

__device__ __forceinline__ void pf1_load(PF1& f, const float* __restrict__ xb,
                                         const __half* __restrict__ w,
                                         int kc, int am, int ach, int tid) {
#pragma unroll
    for (int i = 0; i < 8; i++) {
        int cl = ach * 16 + i * 2;
        float v0 = xb[(size_t)(kc + cl) * HWS + am];
        float v1 = xb[(size_t)(kc + cl + 1) * HWS + am];
        __half2 h = __floats2half2_rn(v0, v1);
        f.a[i] = *reinterpret_cast<uint32_t*>(&h);
    }
#pragma unroll
    for (int j = 0; j < 2; j++) {
        int e = j * 256 + tid;
        int row = e >> 2, ch = e & 3;
        f.b[j] = *(const int4*)(w + (size_t)row * C + kc + ch * 8);
    }
}

__device__ __forceinline__ void pf1_store(const PF1& f, char* base, int am, int ach, int tid) {
#pragma unroll
    for (int i = 0; i < 8; i++) {
        int cl = ach * 16 + i * 2;
        *(uint32_t*)(base + OFF_A + am * ROWB + cl * 2) = f.a[i];
    }
#pragma unroll
    for (int j = 0; j < 2; j++) {
        int e = j * 256 + tid;
        int row = e >> 2, ch = e & 3;
        *(int4*)(base + OFF_B + row * ROWB + ch * 16) = f.b[j];
    }
}

__global__ __launch_bounds__(256) void gemm1_mma(const float* __restrict__ x,
                                                 const float* __restrict__ conv_b) {
    extern __shared__ char sm[];
    const uint32_t smb = smem_u32(sm);
    const int tid = threadIdx.x;
    const int wid = tid >> 5, lane = tid & 31;
    const int warp_m = wid & 3, warp_n = wid >> 2;
    const int lr = lane & 15, lc = lane >> 4;
    const int p0 = blockIdx.x * 128, o0 = blockIdx.y * 128, b = blockIdx.z;

    if (tid < 128) ((float*)(sm + OFF_BIAS))[tid] = conv_b[o0 + tid];

    const float* xb = x + (size_t)b * C * HWS + p0;
    const __half* w = g_w1 + (size_t)o0 * C;
    const int am = tid & 127, ach = tid >> 7;

    float acc[2][8][4];
#pragma unroll
    for (int t = 0; t < 2; t++)
#pragma unroll
        for (int j = 0; j < 8; j++)
#pragma unroll
            for (int q = 0; q < 4; q++) acc[t][j][q] = 0.f;

    PF1 f;
    pf1_load(f, xb, w, 0, am, ach, tid);
    pf1_store(f, sm, am, ach, tid);
    __syncthreads();

    for (int kt = 0; kt < 8; kt++) {
        const int buf = kt & 1;
        if (kt < 7) pf1_load(f, xb, w, (kt + 1) * 32, am, ach, tid);
        mma_chunk(acc, smb + buf * BUFSZ, warp_m, warp_n, lr, lc);
        if (kt < 7) {
            pf1_store(f, sm + (buf ^ 1) * BUFSZ, am, ach, tid);
            __syncthreads();
        }
    }

    // epilogue: write proj fp16 [b][p][o] + bias
    const float* sbias = (const float*)(sm + OFF_BIAS);
    __half* Cb = g_projh + ((size_t)b * HWS + p0) * C + o0;
    const int g4 = lane >> 2, tg = lane & 3;
#pragma unroll
    for (int t = 0; t < 2; t++) {
        const int r0 = warp_m * 32 + t * 16 + g4;
#pragma unroll
        for (int j = 0; j < 8; j++) {
            const int oc = warp_n * 64 + j * 8 + tg * 2;
            float b0 = sbias[oc], b1 = sbias[oc + 1];
            __half2 v0 = __floats2half2_rn(acc[t][j][0] + b0, acc[t][j][1] + b1);
            __half2 v1 = __floats2half2_rn(acc[t][j][2] + b0, acc[t][j][3] + b1);
            *(uint32_t*)(Cb + (size_t)r0 * C + oc) = *reinterpret_cast<uint32_t*>(&v0);
            *(uint32_t*)(Cb + (size_t)(r0 + 8) * C + oc) = *reinterpret_cast<uint32_t*>(&v1);
        }
    }
}

// ---------------- GEMM2: out[b][o][p] = feat @ w2f^T + bias2 ----------------
struct PF2 {
    int4 a[2], b[2];
};

__device__ __forceinline__ void pf2_load(PF2& f, const __half* __restrict__ fh,
                                         const __half* __restrict__ w,
                                         int kc, int tid) {
#pragma unroll
    for (int j = 0; j < 2; j++) {
        int e = j * 256 + tid;
        int row = e >> 2, ch = e & 3;
        f.a[j] = *(const int4*)(fh + (size_t)row * C + kc + ch * 8);
        f.b[j] = *(const int4*)(w + (size_t)row * C + kc + ch * 8);
    }
}

__device__ __forceinline__ void pf2_store(const PF2& f, char* base, int tid) {
#pragma unroll
    for (int j = 0; j < 2; j++) {
        int e = j * 256 + tid;
        int row = e >> 2, ch = e & 3;
        *(int4*)(base + OFF_A + row * ROWB + ch * 16) = f.a[j];
        *(int4*)(base + OFF_B + row * ROWB + ch * 16) = f.b[j];
    }
}

__global__ __launch_bounds__(256) void gemm2_mma(float* __restrict__ out) {
    extern __shared__ char sm[];
    const uint32_t smb = smem_u32(sm);
    const int tid = threadIdx.x;
    const int wid = tid >> 5, lane = tid & 31;
    const int warp_m = wid & 3, warp_n = wid >> 2;
    const int lr = lane & 15, lc = lane >> 4;
    const int p0 = blockIdx.x * 128, o0 = blockIdx.y * 128, b = blockIdx.z;

    if (tid < 128) ((float*)(sm + OFF_BIAS))[tid] = g_bias2[o0 + tid];

    const __half* fh = g_feat + ((size_t)b * HWS + p0) * C;
    const __half* w = g_w2 + (size_t)o0 * C;

    float acc[2][8][4];
#pragma unroll
    for (int t = 0; t < 2; t++)
#pragma unroll
        for (int j = 0; j < 8; j++)
#pragma unroll
            for (int q = 0; q < 4; q++) acc[t][j][q] = 0.f;

    PF2 f;
    pf2_load(f, fh, w, 0, tid);
    pf2_store(f, sm, tid);
    __syncthreads();

    for (int kt = 0; kt < 8; kt++) {
        const int buf = kt & 1;
        if (kt < 7) pf2_load(f, fh, w, (kt + 1) * 32, tid);
        mma_chunk(acc, smb + buf * BUFSZ, warp_m, warp_n, lr, lc);
        if (kt < 7) {
            pf2_store(f, sm + (buf ^ 1) * BUFSZ, tid);
            __syncthreads();
        }
    }

    // epilogue: transpose through smem -> channel-major out[b][o][p]
    __syncthreads();
    float* Cs = (float*)sm;   // 128 x 33 staging
    const float* sbias = (const float*)(sm + OFF_BIAS);
    float* Ob = out + ((size_t)b * C + o0) * HWS + p0;
    const int g4 = lane >> 2, tg = lane & 3;
#pragma unroll
    for (int g = 0; g < 4; g++) {
        if (warp_n == (g >> 1)) {
#pragma unroll
            for (int t = 0; t < 2; t++)
#pragma unroll
                for (int jj = 0; jj < 4; jj++) {
                    const int j = (g & 1) * 4 + jj;
                    const int r = warp_m * 32 + t * 16 + g4;
                    const int cl = jj * 8 + tg * 2;
                    Cs[r * 33 + cl] = acc[t][j][0];
                    Cs[r * 33 + cl + 1] = acc[t][j][1];
                    Cs[(r + 8) * 33 + cl] = acc[t][j][2];
                    Cs[(r + 8) * 33 + cl + 1] = acc[t][j][3];
                }
        }
        __syncthreads();
#pragma unroll
        for (int q = 0; q < 16; q++) {
            const int e = q * 256 + tid;
            const int col = e >> 7, mm = e & 127;
            const int oc = g * 32 + col;
            Ob[(size_t)oc * HWS + mm] = Cs[mm * 33 + col] + sbias[oc];
        }
        __syncthreads();
    }
}

// ---------------- aux: direct-global GEMV, 1 px/thread ----------------
__global__ __launch_bounds__(256) void aux_kernel(
        const float* __restrict__ x,
        const float* __restrict__ off_w, const float* __restrict__ off_b,
        const float* __restrict__ wgt_w, const float* __restrict__ wgt_b) {
    __shared__ float wsi[C * 12];      // interleaved [c][12]
    const int tid = threadIdx.x;
    const int pp = blockIdx.x * 256 + tid;
    const int b = pp >> 14;
    const int p = pp & 16383;

    for (int e = tid; e < 2 * C * KB; e += 256) {      // off_w: [(k*2+d)][c]
        int kd = e >> 8, c = e & 255;
        wsi[c * 12 + kd] = off_w[e];
    }
    for (int e = tid; e < C * KB; e += 256) {          // wgt_w: [k][c]
        int k = e >> 8, c = e & 255;
        wsi[c * 12 + 8 + k] = wgt_w[e];
    }
    __syncthreads();

    float acc[12];
#pragma unroll
    for (int j = 0; j < 12; j++) acc[j] = 0.f;

    const float* xb = x + (size_t)b * C * HWS + p;
#pragma unroll 4
    for (int c = 0; c < C; c++) {
        float xv = xb[(size_t)c * HWS];
        const float4* wp = (const float4*)(wsi + c * 12);
        float4 wa = wp[0], wb = wp[1], wc = wp[2];
        acc[0] = fmaf(xv, wa.x, acc[0]);  acc[1] = fmaf(xv, wa.y, acc[1]);
        acc[2] = fmaf(xv, wa.z, acc[2]);  acc[3] = fmaf(xv, wa.w, acc[3]);
        acc[4] = fmaf(xv, wb.x, acc[4]);  acc[5] = fmaf(xv, wb.y, acc[5]);
        acc[6] = fmaf(xv, wb.z, acc[6]);  acc[7] = fmaf(xv, wb.w, acc[7]);
        acc[8] = fmaf(xv, wc.x, acc[8]);  acc[9] = fmaf(xv, wc.y, acc[9]);
        acc[10] = fmaf(xv, wc.z, acc[10]); acc[11] = fmaf(xv, wc.w, acc[11]);
    }

    const int py = p >> 7, px = p & 127;
    // softmax over 4 logits
    float l0 = acc[8] + wgt_b[0], l1 = acc[9] + wgt_b[1];
    float l2 = acc[10] + wgt_b[2], l3 = acc[11] + wgt_b[3];
    float mx = fmaxf(fmaxf(l0, l1), fmaxf(l2, l3));
    float e0 = __expf(l0 - mx), e1 = __expf(l1 - mx);
    float e2 = __expf(l2 - mx), e3 = __expf(l3 - mx);
    float invs = 1.f / (e0 + e1 + e2 + e3);
    float wk4[4] = {e0 * invs, e1 * invs, e2 * invs, e3 * invs};
#pragma unroll
    for (int k = 0; k < KB; k++) {
        float vx = (float)px + acc[2 * k] + off_b[2 * k];
        float vy = (float)py + acc[2 * k + 1] + off_b[2 * k + 1];
        float x0f = floorf(vx), y0f = floorf(vy);
        float wx1 = vx - x0f, wy1 = vy - y0f;
        int x0 = (int)x0f, y0 = (int)y0f;
        bool vx0 = (x0 >= 0) && (x0 <= WW - 1);
        bool vx1 = (x0 + 1 >= 0) && (x0 + 1 <= WW - 1);
        bool vy0 = (y0 >= 0) && (y0 <= HH - 1);
        bool vy1 = (y0 + 1 >= 0) && (y0 + 1 <= HH - 1);
        float wk = wk4[k];
        float w00 = (1.f - wx1) * (1.f - wy1) * wk * (float)(vx0 && vy0);
        float w01 = wx1 * (1.f - wy1) * wk * (float)(vx1 && vy0);
        float w10 = (1.f - wx1) * wy1 * wk * (float)(vx0 && vy1);
        float w11 = wx1 * wy1 * wk * (float)(vx1 && vy1);
        int xc0 = min(max(x0, 0), WW - 1);
        int xc1 = min(max(x0 + 1, 0), WW - 1);
        int yc0 = min(max(y0, 0), HH - 1);
        int yc1 = min(max(y0 + 1, 0), HH - 1);
        size_t off = ((size_t)(b * KB + k)) * HWS + p;
        g_idx[off] = make_int4(yc0 * WW + xc0, yc0 * WW + xc1,
                               yc1 * WW + xc0, yc1 * WW + xc1);
        g_cw[off] = make_float4(w00, w01, w10, w11);
    }
}

// ---------------- sampling: feat = proj + weighted gather (fp16 proj) ----------------
__device__ __forceinline__ void acc_row(float* acc, uint4 v, float w) {
    const __half2* h = reinterpret_cast<const __half2*>(&v);
#pragma unroll
    for (int i = 0; i < 4; i++) {
        float2 f = __half22float2(h[i]);
        acc[2 * i]     = fmaf(w, f.x, acc[2 * i]);
        acc[2 * i + 1] = fmaf(w, f.y, acc[2 * i + 1]);
    }
}

__global__ void sample_kernel() {
    const int warp = threadIdx.x >> 5;
    const int lane = threadIdx.x & 31;
    const size_t pp = (size_t)blockIdx.x * 8 + warp;
    const int b = (int)(pp >> 14);
    const int p = (int)(pp & 16383);

    const uint4* projb = (const uint4*)g_projh + (size_t)b * HWS * 32;  // 32 uint4/row
    float acc[8];
    {
        uint4 sv = projb[(size_t)p * 32 + lane];
        const __half2* h = reinterpret_cast<const __half2*>(&sv);
#pragma unroll
        for (int i = 0; i < 4; i++) {
            float2 f = __half22float2(h[i]);
            acc[2 * i] = f.x;
            acc[2 * i + 1] = f.y;
        }
    }

    const size_t kb = (size_t)b * KB * HWS + p;
#pragma unroll
    for (int k = 0; k < KB; k++) {
        int4 id = g_idx[kb + (size_t)k * HWS];
        float4 w = g_cw[kb + (size_t)k * HWS];
        uint4 v0 = projb[(size_t)id.x * 32 + lane];
        uint4 v1 = projb[(size_t)id.y * 32 + lane];
        uint4 v2 = projb[(size_t)id.z * 32 + lane];
        uint4 v3 = projb[(size_t)id.w * 32 + lane];
        acc_row(acc, v0, w.x);
        acc_row(acc, v1, w.y);
        acc_row(acc, v2, w.z);
        acc_row(acc, v3, w.w);
    }

    __half2 o[4];
#pragma unroll
    for (int i = 0; i < 4; i++)
        o[i] = __floats2half2_rn(acc[2 * i], acc[2 * i + 1]);
    ((uint4*)g_feat)[((size_t)b * HWS + p) * 32 + lane] = *reinterpret_cast<uint4*>(o);
}

// ---------------- launch ----------------
extern "C" void kernel_launch(void* const* d_in, const int* in_sizes, int n_in,
                              void* d_out, int out_size) {
    (void)in_sizes; (void)n_in; (void)out_size;
    const float* x      = (const float*)d_in[0];
    const float* conv_w = (const float*)d_in[1];
    const float* conv_b = (const float*)d_in[2];
    const float* off_w  = (const float*)d_in[3];
    const float* off_b  = (const float*)d_in[4];
    const float* wgt_w  = (const float*)d_in[5];
    const float* wgt_b  = (const float*)d_in[6];
    const float* gamma  = (const float*)d_in[7];
    const float* beta   = (const float*)d_in[8];
    const float* rmean  = (const float*)d_in[9];
    const float* rvar   = (const float*)d_in[10];
    const float* out_w  = (const float*)d_in[11];
    const float* out_b  = (const float*)d_in[12];
    float* out = (float*)d_out;

    static bool attr_done = false;
    if (!attr_done) {
        cudaFuncSetAttribute(gemm1_mma, cudaFuncAttributeMaxDynamicSharedMemorySize, GEMM_SMEM);
        cudaFuncSetAttribute(gemm2_mma, cudaFuncAttributeMaxDynamicSharedMemorySize, GEMM_SMEM);
        attr_done = true;
    }

    prep_kernel<<<C, C>>>(conv_w, out_w, out_b, gamma, beta, rmean, rvar);
    gemm1_mma<<<dim3(HWS / 128, C / 128, BATCH), 256, GEMM_SMEM>>>(x, conv_b);
    aux_kernel<<<NPX / 256, 256>>>(x, off_w, off_b, wgt_w, wgt_b);
    sample_kernel<<<NPX / 8, 256>>>();
    gemm2_mma<<<dim3(HWS / 128, C / 128, BATCH), 256, GEMM_SMEM>>>(out);
}

// round 7
// speedup vs baseline: 3.1581x; 1.1314x over previous
#include <cuda_runtime.h>
#include <cuda_fp16.h>
#include <cstdint>

// Problem constants
#define BATCH 8
#define C 256
#define KB 4
#define HH 128
#define WW 128
#define HWS 16384
#define NPX (BATCH*HWS)

// ---------------- device scratch ----------------
__device__ __align__(16) __half g_projh[(size_t)NPX * C]; // proj fp16 [b][p][c]
__device__ __align__(16) __half g_w1[C * C];              // conv_w fp16 [o][c]
__device__ __align__(16) __half g_w2[C * C];              // BN-folded out_w fp16 [o][c]
__device__ float g_bias2[C];
__device__ float4 g_cw[(size_t)BATCH * KB * HWS];
__device__ int4   g_idx[(size_t)BATCH * KB * HWS];

// ---------------- helpers ----------------
__device__ __forceinline__ uint32_t smem_u32(const void* p) {
    uint32_t a;
    asm("{ .reg .u64 t; cvta.to.shared.u64 t, %1; cvt.u32.u64 %0, t; }" : "=r"(a) : "l"(p));
    return a;
}

__device__ __forceinline__ void ldsm4(uint32_t* r, uint32_t addr) {
    asm volatile("ldmatrix.sync.aligned.m8n8.x4.shared.b16 {%0,%1,%2,%3}, [%4];"
                 : "=r"(r[0]), "=r"(r[1]), "=r"(r[2]), "=r"(r[3]) : "r"(addr));
}

__device__ __forceinline__ void mma_fp16(float* d, const uint32_t* a, uint32_t b0, uint32_t b1) {
    asm volatile(
        "mma.sync.aligned.m16n8k16.row.col.f32.f16.f16.f32 "
        "{%0,%1,%2,%3}, {%4,%5,%6,%7}, {%8,%9}, {%0,%1,%2,%3};"
        : "+f"(d[0]), "+f"(d[1]), "+f"(d[2]), "+f"(d[3])
        : "r"(a[0]), "r"(a[1]), "r"(a[2]), "r"(a[3]), "r"(b0), "r"(b1));
}

// ============ GEMM1 (unchanged shape): tile 128x128, BK=32, 256 thr ============
#define ROWB 80
#define TSZ  (128 * ROWB)
#define BUFSZ (2 * TSZ)
#define OFF_A  0
#define OFF_B  TSZ
#define OFF_BIAS (2 * BUFSZ)
#define GEMM_SMEM (OFF_BIAS + 1024)

// ============ fused GEMM2: tile 128px x 256out, 512 thr ============
#define A_PITCH 528                       // 256 halves + 16B pad -> ldsm conflict-free
#define A_SZ (128 * A_PITCH)              // 67584
#define B_PITCH 48                        // 16 halves + 16B pad -> ldsm conflict-free
#define B_TSZ (256 * B_PITCH)             // 12288
#define OFF2_B A_SZ
#define OFF2_BIAS (A_SZ + 2 * B_TSZ)      // 92160
#define GEMM2_SMEM (OFF2_BIAS + 1024)     // 93184

// ---------------- prep: weights to fp16, fold BN ----------------
__global__ void prep_kernel(const float* __restrict__ conv_w,
                            const float* __restrict__ out_w, const float* __restrict__ out_b,
                            const float* __restrict__ gamma, const float* __restrict__ beta,
                            const float* __restrict__ rmean, const float* __restrict__ rvar) {
    int o = blockIdx.x;
    int c = threadIdx.x;
    __shared__ float red[C];
    g_w1[o * C + c] = __float2half_rn(conv_w[o * C + c]);

    float inv = gamma[c] / sqrtf(rvar[c] + 1e-5f);
    float w = out_w[o * C + c];
    g_w2[o * C + c] = __float2half_rn(w * inv);

    red[c] = w * (beta[c] - rmean[c] * inv);
    __syncthreads();
    for (int s = 128; s > 0; s >>= 1) {
        if (c < s) red[c] += red[c + s];
        __syncthreads();
    }
    if (c == 0) g_bias2[o] = red[0] + out_b[o];
}

// ---------------- GEMM1: proj[b][p][o] = x^T @ conv_w^T + conv_b ----------------
struct PF1 {
    uint32_t a[8];
    int4 b[2];
};

__device__ __forceinline__ void pf1_load(PF1& f, const float* __restrict__ xb,
                                         const __half* __restrict__ w,
                                         int kc, int am, int ach, int tid) {
#pragma unroll
    for (int i = 0; i < 8; i++) {
        int cl = ach * 16 + i * 2;
        float v0 = xb[(size_t)(kc + cl) * HWS + am];
        float v1 = xb[(size_t)(kc + cl + 1) * HWS + am];
        __half2 h = __floats2half2_rn(v0, v1);
        f.a[i] = *reinterpret_cast<uint32_t*>(&h);
    }
#pragma unroll
    for (int j = 0; j < 2; j++) {
        int e = j * 256 + tid;
        int row = e >> 2, ch = e & 3;
        f.b[j] = *(const int4*)(w + (size_t)row * C + kc + ch * 8);
    }
}

__device__ __forceinline__ void pf1_store(const PF1& f, char* base, int am, int ach, int tid) {
#pragma unroll
    for (int i = 0; i < 8; i++) {
        int cl = ach * 16 + i * 2;
        *(uint32_t*)(base + OFF_A + am * ROWB + cl * 2) = f.a[i];
    }
#pragma unroll
    for (int j = 0; j < 2; j++) {
        int e = j * 256 + tid;
        int row = e >> 2, ch = e & 3;
        *(int4*)(base + OFF_B + row * ROWB + ch * 16) = f.b[j];
    }
}

__global__ __launch_bounds__(256) void gemm1_mma(const float* __restrict__ x,
                                                 const float* __restrict__ conv_b) {
    extern __shared__ char sm[];
    const uint32_t smb = smem_u32(sm);
    const int tid = threadIdx.x;
    const int wid = tid >> 5, lane = tid & 31;
    const int warp_m = wid & 3, warp_n = wid >> 2;
    const int lr = lane & 15, lc = lane >> 4;
    const int p0 = blockIdx.x * 128, o0 = blockIdx.y * 128, b = blockIdx.z;

    if (tid < 128) ((float*)(sm + OFF_BIAS))[tid] = conv_b[o0 + tid];

    const float* xb = x + (size_t)b * C * HWS + p0;
    const __half* w = g_w1 + (size_t)o0 * C;
    const int am = tid & 127, ach = tid >> 7;

    float acc[2][8][4];
#pragma unroll
    for (int t = 0; t < 2; t++)
#pragma unroll
        for (int j = 0; j < 8; j++)
#pragma unroll
            for (int q = 0; q < 4; q++) acc[t][j][q] = 0.f;

    PF1 f;
    pf1_load(f, xb, w, 0, am, ach, tid);
    pf1_store(f, sm, am, ach, tid);
    __syncthreads();

    for (int kt = 0; kt < 8; kt++) {
        const int buf = kt & 1;
        if (kt < 7) pf1_load(f, xb, w, (kt + 1) * 32, am, ach, tid);
        {
            const uint32_t smbuf = smb + buf * BUFSZ;
            const uint32_t a_base = smbuf + OFF_A + (uint32_t)(warp_m * 32 + lr) * ROWB + lc * 16;
            const uint32_t b_base = smbuf + OFF_B + (uint32_t)(warp_n * 64 + lr) * ROWB + lc * 16;
#pragma unroll
            for (int s = 0; s < 2; s++) {
                uint32_t a[2][4], bb[4][4];
#pragma unroll
                for (int t = 0; t < 2; t++)
                    ldsm4(a[t], a_base + t * (16 * ROWB) + s * 32);
#pragma unroll
                for (int u = 0; u < 4; u++)
                    ldsm4(bb[u], b_base + u * (16 * ROWB) + s * 32);
#pragma unroll
                for (int t = 0; t < 2; t++)
#pragma unroll
                    for (int u = 0; u < 4; u++) {
                        mma_fp16(acc[t][u * 2], a[t], bb[u][0], bb[u][2]);
                        mma_fp16(acc[t][u * 2 + 1], a[t], bb[u][1], bb[u][3]);
                    }
            }
        }
        if (kt < 7) {
            pf1_store(f, sm + (buf ^ 1) * BUFSZ, am, ach, tid);
            __syncthreads();
        }
    }

    // epilogue: write proj fp16 [b][p][o] + bias
    const float* sbias = (const float*)(sm + OFF_BIAS);
    __half* Cb = g_projh + ((size_t)b * HWS + p0) * C + o0;
    const int g4 = lane >> 2, tg = lane & 3;
#pragma unroll
    for (int t = 0; t < 2; t++) {
        const int r0 = warp_m * 32 + t * 16 + g4;
#pragma unroll
        for (int j = 0; j < 8; j++) {
            const int oc = warp_n * 64 + j * 8 + tg * 2;
            float b0 = sbias[oc], b1 = sbias[oc + 1];
            __half2 v0 = __floats2half2_rn(acc[t][j][0] + b0, acc[t][j][1] + b1);
            __half2 v1 = __floats2half2_rn(acc[t][j][2] + b0, acc[t][j][3] + b1);
            *(uint32_t*)(Cb + (size_t)r0 * C + oc) = *reinterpret_cast<uint32_t*>(&v0);
            *(uint32_t*)(Cb + (size_t)(r0 + 8) * C + oc) = *reinterpret_cast<uint32_t*>(&v1);
        }
    }
}

// ---------------- aux: direct-global GEMV, 1 px/thread ----------------
__global__ __launch_bounds__(256) void aux_kernel(
        const float* __restrict__ x,
        const float* __restrict__ off_w, const float* __restrict__ off_b,
        const float* __restrict__ wgt_w, const float* __restrict__ wgt_b) {
    __shared__ float wsi[C * 12];      // interleaved [c][12]
    const int tid = threadIdx.x;
    const int pp = blockIdx.x * 256 + tid;
    const int b = pp >> 14;
    const int p = pp & 16383;

    for (int e = tid; e < 2 * C * KB; e += 256) {
        int kd = e >> 8, c = e & 255;
        wsi[c * 12 + kd] = off_w[e];
    }
    for (int e = tid; e < C * KB; e += 256) {
        int k = e >> 8, c = e & 255;
        wsi[c * 12 + 8 + k] = wgt_w[e];
    }
    __syncthreads();

    float acc[12];
#pragma unroll
    for (int j = 0; j < 12; j++) acc[j] = 0.f;

    const float* xb = x + (size_t)b * C * HWS + p;
#pragma unroll 4
    for (int c = 0; c < C; c++) {
        float xv = xb[(size_t)c * HWS];
        const float4* wp = (const float4*)(wsi + c * 12);
        float4 wa = wp[0], wb = wp[1], wc = wp[2];
        acc[0] = fmaf(xv, wa.x, acc[0]);  acc[1] = fmaf(xv, wa.y, acc[1]);
        acc[2] = fmaf(xv, wa.z, acc[2]);  acc[3] = fmaf(xv, wa.w, acc[3]);
        acc[4] = fmaf(xv, wb.x, acc[4]);  acc[5] = fmaf(xv, wb.y, acc[5]);
        acc[6] = fmaf(xv, wb.z, acc[6]);  acc[7] = fmaf(xv, wb.w, acc[7]);
        acc[8] = fmaf(xv, wc.x, acc[8]);  acc[9] = fmaf(xv, wc.y, acc[9]);
        acc[10] = fmaf(xv, wc.z, acc[10]); acc[11] = fmaf(xv, wc.w, acc[11]);
    }

    const int py = p >> 7, px = p & 127;
    float l0 = acc[8] + wgt_b[0], l1 = acc[9] + wgt_b[1];
    float l2 = acc[10] + wgt_b[2], l3 = acc[11] + wgt_b[3];
    float mx = fmaxf(fmaxf(l0, l1), fmaxf(l2, l3));
    float e0 = __expf(l0 - mx), e1 = __expf(l1 - mx);
    float e2 = __expf(l2 - mx), e3 = __expf(l3 - mx);
    float invs = 1.f / (e0 + e1 + e2 + e3);
    float wk4[4] = {e0 * invs, e1 * invs, e2 * invs, e3 * invs};
#pragma unroll
    for (int k = 0; k < KB; k++) {
        float vx = (float)px + acc[2 * k] + off_b[2 * k];
        float vy = (float)py + acc[2 * k + 1] + off_b[2 * k + 1];
        float x0f = floorf(vx), y0f = floorf(vy);
        float wx1 = vx - x0f, wy1 = vy - y0f;
        int x0 = (int)x0f, y0 = (int)y0f;
        bool vx0 = (x0 >= 0) && (x0 <= WW - 1);
        bool vx1 = (x0 + 1 >= 0) && (x0 + 1 <= WW - 1);
        bool vy0 = (y0 >= 0) && (y0 <= HH - 1);
        bool vy1 = (y0 + 1 >= 0) && (y0 + 1 <= HH - 1);
        float wk = wk4[k];
        float w00 = (1.f - wx1) * (1.f - wy1) * wk * (float)(vx0 && vy0);
        float w01 = wx1 * (1.f - wy1) * wk * (float)(vx1 && vy0);
        float w10 = (1.f - wx1) * wy1 * wk * (float)(vx0 && vy1);
        float w11 = wx1 * wy1 * wk * (float)(vx1 && vy1);
        int xc0 = min(max(x0, 0), WW - 1);
        int xc1 = min(max(x0 + 1, 0), WW - 1);
        int yc0 = min(max(y0, 0), HH - 1);
        int yc1 = min(max(y0 + 1, 0), HH - 1);
        size_t off = ((size_t)(b * KB + k)) * HWS + p;
        g_idx[off] = make_int4(yc0 * WW + xc0, yc0 * WW + xc1,
                               yc1 * WW + xc0, yc1 * WW + xc1);
        g_cw[off] = make_float4(w00, w01, w10, w11);
    }
}

// ---------------- fused GEMM2: gather feat tile in smem, then 128x256 GEMM ----------------
__device__ __forceinline__ void acc_row(float* acc, uint4 v, float w) {
    const __half2* h = reinterpret_cast<const __half2*>(&v);
#pragma unroll
    for (int i = 0; i < 4; i++) {
        float2 f = __half22float2(h[i]);
        acc[2 * i]     = fmaf(w, f.x, acc[2 * i]);
        acc[2 * i + 1] = fmaf(w, f.y, acc[2 * i + 1]);
    }
}

__global__ __launch_bounds__(512) void gemm2_fused(float* __restrict__ out) {
    extern __shared__ char sm[];
    const uint32_t smb = smem_u32(sm);
    const int tid = threadIdx.x;
    const int wid = tid >> 5, lane = tid & 31;
    const int warp_m = wid & 3, warp_n = wid >> 2;
    const int lr = lane & 15, lc = lane >> 4;
    const int p0 = blockIdx.x * 128, b = blockIdx.y;

    if (tid < 256) ((float*)(sm + OFF2_BIAS))[tid] = g_bias2[tid];

    // ---- gather phase: build feat A tile [128 px][256 ch] fp16 in smem ----
    const uint4* projb = (const uint4*)g_projh + (size_t)b * HWS * 32;
#pragma unroll
    for (int i = 0; i < 8; i++) {
        const int px = wid * 8 + i;
        const int p = p0 + px;
        float acc[8];
        {
            uint4 sv = projb[(size_t)p * 32 + lane];
            const __half2* h = reinterpret_cast<const __half2*>(&sv);
#pragma unroll
            for (int q = 0; q < 4; q++) {
                float2 f = __half22float2(h[q]);
                acc[2 * q] = f.x;
                acc[2 * q + 1] = f.y;
            }
        }
        const size_t kb = (size_t)b * KB * HWS + p;
#pragma unroll
        for (int k = 0; k < KB; k++) {
            int4 id = g_idx[kb + (size_t)k * HWS];
            float4 w = g_cw[kb + (size_t)k * HWS];
            uint4 v0 = projb[(size_t)id.x * 32 + lane];
            uint4 v1 = projb[(size_t)id.y * 32 + lane];
            uint4 v2 = projb[(size_t)id.z * 32 + lane];
            uint4 v3 = projb[(size_t)id.w * 32 + lane];
            acc_row(acc, v0, w.x);
            acc_row(acc, v1, w.y);
            acc_row(acc, v2, w.z);
            acc_row(acc, v3, w.w);
        }
        __half2 o[4];
#pragma unroll
        for (int q = 0; q < 4; q++)
            o[q] = __floats2half2_rn(acc[2 * q], acc[2 * q + 1]);
        *(uint4*)(sm + px * A_PITCH + lane * 16) = *reinterpret_cast<uint4*>(o);
    }

    // ---- prefetch B chunk 0 ----
    const __half* w2 = g_w2;
    const int brow = tid >> 1, bch = tid & 1;
    int4 bv = *(const int4*)(w2 + (size_t)brow * C + bch * 8);
    *(int4*)(sm + OFF2_B + brow * B_PITCH + bch * 16) = bv;
    __syncthreads();

    float acc[2][8][4];
#pragma unroll
    for (int t = 0; t < 2; t++)
#pragma unroll
        for (int j = 0; j < 8; j++)
#pragma unroll
            for (int q = 0; q < 4; q++) acc[t][j][q] = 0.f;

    for (int kt = 0; kt < 16; kt++) {
        const int buf = kt & 1;
        if (kt < 15)
            bv = *(const int4*)(w2 + (size_t)brow * C + (kt + 1) * 16 + bch * 8);
        {
            const uint32_t a_base = smb + (uint32_t)(warp_m * 32 + lr) * A_PITCH + kt * 32 + lc * 16;
            const uint32_t b_base = smb + OFF2_B + buf * B_TSZ +
                                    (uint32_t)(warp_n * 64 + lr) * B_PITCH + lc * 16;
            uint32_t a[2][4], bb[4][4];
#pragma unroll
            for (int t = 0; t < 2; t++)
                ldsm4(a[t], a_base + t * (16 * A_PITCH));
#pragma unroll
            for (int u = 0; u < 4; u++)
                ldsm4(bb[u], b_base + u * (16 * B_PITCH));
#pragma unroll
            for (int t = 0; t < 2; t++)
#pragma unroll
                for (int u = 0; u < 4; u++) {
                    mma_fp16(acc[t][u * 2], a[t], bb[u][0], bb[u][2]);
                    mma_fp16(acc[t][u * 2 + 1], a[t], bb[u][1], bb[u][3]);
                }
        }
        if (kt < 15) {
            *(int4*)(sm + OFF2_B + (buf ^ 1) * B_TSZ + brow * B_PITCH + bch * 16) = bv;
            __syncthreads();
        }
    }

    // ---- epilogue: transpose through smem (reuse A region) -> out[b][o][p] ----
    __syncthreads();
    float* Cs = (float*)sm;   // 128 x 33 staging
    const float* sbias = (const float*)(sm + OFF2_BIAS);
    float* Ob = out + (size_t)b * C * HWS + p0;
    const int g4 = lane >> 2, tg = lane & 3;
#pragma unroll
    for (int g = 0; g < 8; g++) {
        if (warp_n == (g >> 1)) {
#pragma unroll
            for (int t = 0; t < 2; t++)
#pragma unroll
                for (int jj = 0; jj < 4; jj++) {
                    const int j = (g & 1) * 4 + jj;
                    const int r = warp_m * 32 + t * 16 + g4;
                    const int cl = jj * 8 + tg * 2;
                    Cs[r * 33 + cl] = acc[t][j][0];
                    Cs[r * 33 + cl + 1] = acc[t][j][1];
                    Cs[(r + 8) * 33 + cl] = acc[t][j][2];
                    Cs[(r + 8) * 33 + cl + 1] = acc[t][j][3];
                }
        }
        __syncthreads();
#pragma unroll
        for (int q = 0; q < 8; q++) {
            const int e = q * 512 + tid;
            const int col = e >> 7, mm = e & 127;
            const int oc = g * 32 + col;
            Ob[(size_t)oc * HWS + mm] = Cs[mm * 33 + col] + sbias[oc];
        }
        __syncthreads();
    }
}

// ---------------- launch ----------------
extern "C" void kernel_launch(void* const* d_in, const int* in_sizes, int n_in,
                              void* d_out, int out_size) {
    (void)in_sizes; (void)n_in; (void)out_size;
    const float* x      = (const float*)d_in[0];
    const float* conv_w = (const float*)d_in[1];
    const float* conv_b = (const float*)d_in[2];
    const float* off_w  = (const float*)d_in[3];
    const float* off_b  = (const float*)d_in[4];
    const float* wgt_w  = (const float*)d_in[5];
    const float* wgt_b  = (const float*)d_in[6];
    const float* gamma  = (const float*)d_in[7];
    const float* beta   = (const float*)d_in[8];
    const float* rmean  = (const float*)d_in[9];
    const float* rvar   = (const float*)d_in[10];
    const float* out_w  = (const float*)d_in[11];
    const float* out_b  = (const float*)d_in[12];
    float* out = (float*)d_out;

    static bool attr_done = false;
    if (!attr_done) {
        cudaFuncSetAttribute(gemm1_mma, cudaFuncAttributeMaxDynamicSharedMemorySize, GEMM_SMEM);
        cudaFuncSetAttribute(gemm2_fused, cudaFuncAttributeMaxDynamicSharedMemorySize, GEMM2_SMEM);
        attr_done = true;
    }

    prep_kernel<<<C, C>>>(conv_w, out_w, out_b, gamma, beta, rmean, rvar);
    gemm1_mma<<<dim3(HWS / 128, C / 128, BATCH), 256, GEMM_SMEM>>>(x, conv_b);
    aux_kernel<<<NPX / 256, 256>>>(x, off_w, off_b, wgt_w, wgt_b);
    gemm2_fused<<<dim3(HWS / 128, BATCH), 512, GEMM2_SMEM>>>(out);
}